// round 11
// baseline (speedup 1.0000x reference)
#include <cuda_runtime.h>
#include <cuda_bf16.h>
#include <math.h>
#include <stdint.h>

#define BB 32
#define NREG 196
#define EE 512
#define HH 512
#define SEQ 64
#define VV 32000

#define NBLK 148
#define NTHR 1024

// ---------------- scratch (device globals; no allocations) ----------------
__device__ float g_fmean[BB * EE];
__device__ __align__(16) float g_hbuf[2][BB * HH];   // [b][k]   (attention)
__device__ __align__(16) float g_hT[2][HH * BB];     // [k][b]   (gate GEMV)
__device__ float g_cT[HH * BB];                      // [k][b]
__device__ __align__(16) float g_actCE[2 * EE * BB]; // [k][b]: k<512 ctx, k>=512 emb*sqrtE
__device__ __align__(16) float g_actX[EE * BB];      // [k][b]: x
__device__ __align__(16) float g_Hall[SEQ * BB * HH];// row (t*32+b)
__device__ unsigned g_bar_count;
__device__ unsigned g_bar_gen;

// bf16 split buffers for tensor-core GEMM
__device__ __align__(16) __nv_bfloat16 g_AH[SEQ * BB * HH];
__device__ __align__(16) __nv_bfloat16 g_AL[SEQ * BB * HH];
__device__ __align__(16) __nv_bfloat16 g_WH[(size_t)VV * EE];
__device__ __align__(16) __nv_bfloat16 g_WL[(size_t)VV * EE];

// ---------------- grid-wide barrier ----------------
__device__ __forceinline__ void gridbar() {
    __syncthreads();
    if (threadIdx.x == 0) {
        unsigned gen = *((volatile unsigned*)&g_bar_gen);
        __threadfence();
        if (atomicAdd(&g_bar_count, 1u) == (unsigned)(gridDim.x - 1)) {
            g_bar_count = 0;
            __threadfence();
            atomicAdd(&g_bar_gen, 1u);
        } else {
            while (*((volatile unsigned*)&g_bar_gen) == gen) { __nanosleep(32); }
        }
        __threadfence();
    }
    __syncthreads();
}

__device__ __forceinline__ float warpsum(float v) {
#pragma unroll
    for (int o = 16; o; o >>= 1) v += __shfl_xor_sync(0xffffffffu, v, o);
    return v;
}

__device__ __forceinline__ float warpdot512(const float* __restrict__ a,
                                            const float* __restrict__ b, int lane) {
    float s = 0.f;
#pragma unroll
    for (int c = 0; c < 4; c++) {
        float4 av = *(const float4*)(a + c * 128 + lane * 4);
        float4 bv = *(const float4*)(b + c * 128 + lane * 4);
        s += av.x * bv.x + av.y * bv.y + av.z * bv.z + av.w * bv.w;
    }
    return s;
}

// smem pool (floats):
// P12:  h[512]@0 | sc[256]@512 | attn[256]@768 | red[32]@1024 | part[32*128]@1056  (5152)
// GEMV: act[4096]@0 | w[2048]@4096 | red[4096]@6144 | out[512]@10240             (10752)
#define POOL_F 10752

// ---------------- persistent recurrence kernel ----------------
__global__ void __launch_bounds__(NTHR) recurrence_kernel(
    const float* __restrict__ features, const int* __restrict__ captions,
    const float* __restrict__ embed_W,
    const float* __restrict__ ihW, const float* __restrict__ ihb,
    const float* __restrict__ icW, const float* __restrict__ icb,
    const float* __restrict__ rW,  const float* __restrict__ rb,
    const float* __restrict__ Wih, const float* __restrict__ Whh,
    const float* __restrict__ bih, const float* __restrict__ bhh)
{
    const int tid  = threadIdx.x;
    const int lane = tid & 31;
    const int w    = tid >> 5;
    const int gtid = blockIdx.x * NTHR + tid;
    const int wid_g  = gtid >> 5;
    const int nwarps = (NBLK * NTHR) >> 5;
    const int gstride = NBLK * NTHR;

    __shared__ __align__(16) float pool[POOL_F];
    float* sh_h  = pool;            // 512
    float* sSc   = pool + 512;      // 256
    float* sAttn = pool + 768;      // 256
    float* sRedS = pool + 1024;     // 32
    float* sPart = pool + 1056;     // 4096 (32 warps x 128)
    float* sAct  = pool;            // 4096
    float* sW    = pool + 4096;     // 2048
    float* sRed  = pool + 6144;     // 4096
    float* sOut  = pool + 10240;    // 512

    // ---- init a: fmean
    for (int idx = gtid; idx < BB * EE; idx += gstride) {
        int b = idx >> 9, e = idx & 511;
        const float* fp = features + (size_t)b * NREG * EE + e;
        float s = 0.f;
        for (int n = 0; n < NREG; n++) s += fp[n * EE];
        g_fmean[idx] = s * (1.0f / NREG);
    }
    gridbar();

    // ---- init b: h0 / c0 (warp per output)
    for (int task = wid_g; task < 2 * BB * HH; task += nwarps) {
        int which = task & 1;
        int m = task >> 1;
        int b = m >> 9, eo = m & 511;
        const float* Wrow = (which ? icW : ihW) + (size_t)eo * EE;
        float s = warpsum(warpdot512(Wrow, g_fmean + b * EE, lane));
        if (lane == 0) {
            if (which) {
                g_cT[eo * BB + b] = s + icb[eo];
            } else {
                float hv = s + ihb[eo];
                g_hbuf[0][m] = hv;
                g_hT[0][eo * BB + b] = hv;
            }
        }
    }
    gridbar();

    for (int t = 0; t < SEQ; t++) {
        const float* h_cur  = g_hbuf[t & 1];
        const float* hT_cur = g_hT[t & 1];
        float*       h_nxt  = g_hbuf[(t & 1) ^ 1];
        float*       hT_nxt = g_hT[(t & 1) ^ 1];

        // ==== P12: attention, scores redundant per (b,chunk) block + emb fill
        if (blockIdx.x < 128) {
            const int b = blockIdx.x >> 2;
            const int chunk = blockIdx.x & 3;
            const float* fb = features + (size_t)b * NREG * EE;

            if (tid < EE) sh_h[tid] = h_cur[b * EE + tid];
            __syncthreads();

            for (int n = w; n < NREG; n += 32) {
                float s = warpsum(warpdot512(fb + (size_t)n * EE, sh_h, lane));
                if (lane == 0) sSc[n] = s;
            }
            __syncthreads();

            float v = (tid < NREG) ? sSc[tid] : -1e30f;
            float m = v;
#pragma unroll
            for (int o = 16; o; o >>= 1) m = fmaxf(m, __shfl_xor_sync(0xffffffffu, m, o));
            if (lane == 0) sRedS[w] = m;
            __syncthreads();
            float mx = sRedS[0];
#pragma unroll
            for (int i = 1; i < 32; i++) mx = fmaxf(mx, sRedS[i]);
            float ev = (tid < NREG) ? __expf(v - mx) : 0.f;
            float ps = warpsum(ev);
            __syncthreads();
            if (lane == 0) sRedS[w] = ps;
            __syncthreads();
            float tot = 0.f;
#pragma unroll
            for (int i = 0; i < 32; i++) tot += sRedS[i];
            if (tid < NREG) sAttn[tid] = ev / tot;
            __syncthreads();

            float4 cacc = make_float4(0.f, 0.f, 0.f, 0.f);
            const float* fc = fb + chunk * 128 + lane * 4;
            for (int n = w; n < NREG; n += 32) {
                float a = sAttn[n];
                float4 fv = *(const float4*)(fc + (size_t)n * EE);
                cacc.x += a * fv.x; cacc.y += a * fv.y;
                cacc.z += a * fv.z; cacc.w += a * fv.w;
            }
            *(float4*)(sPart + w * 128 + lane * 4) = cacc;
            __syncthreads();
            if (tid < 128) {
                float s = 0.f;
#pragma unroll
                for (int i = 0; i < 32; i++) s += sPart[i * 128 + tid];
                g_actCE[(chunk * 128 + tid) * BB + b] = s;
            }
        } else {
            for (int idx = (blockIdx.x - 128) * NTHR + tid; idx < BB * EE;
                 idx += 20 * NTHR) {
                int b = idx >> 9, k = idx & 511;
                int tok = captions[b * SEQ + t];
                g_actCE[(EE + k) * BB + b] =
                    embed_W[(size_t)tok * EE + k] * 22.62741699796952f; // sqrt(512)
            }
        }
        gridbar();

        // ==== P3: x = rW @ [ctx; emb] + rb  (128 blocks x 4 rows; warp = 4-K slice,
        //          computes ALL 4 rows per act read — register-blocked)
        if (blockIdx.x < 128) {
            const int r0 = blockIdx.x * 4;
            float acc0 = 0.f, acc1 = 0.f, acc2 = 0.f, acc3 = 0.f;
            for (int kc = 0; kc < 8; kc++) {
                __syncthreads();
                const float* asrc = g_actCE + kc * 128 * BB;
                ((float4*)sAct)[tid] = ((const float4*)asrc)[tid];
                if (tid < 512) {
                    int r = tid >> 7, k = tid & 127;
                    sW[tid] = rW[(size_t)(r0 + r) * (EE + HH) + kc * 128 + k];
                }
                __syncthreads();
                const int kb = w * 4;     // this warp's 4 K-positions in the chunk
                const float* ap = sAct + kb * BB + lane;
                float a0 = ap[0 * BB], a1 = ap[1 * BB];
                float a2 = ap[2 * BB], a3 = ap[3 * BB];
                float4 w0 = *(const float4*)(sW + 0 * 128 + kb);
                float4 w1 = *(const float4*)(sW + 1 * 128 + kb);
                float4 w2 = *(const float4*)(sW + 2 * 128 + kb);
                float4 w3 = *(const float4*)(sW + 3 * 128 + kb);
                acc0 += w0.x * a0 + w0.y * a1 + w0.z * a2 + w0.w * a3;
                acc1 += w1.x * a0 + w1.y * a1 + w1.z * a2 + w1.w * a3;
                acc2 += w2.x * a0 + w2.y * a1 + w2.z * a2 + w2.w * a3;
                acc3 += w3.x * a0 + w3.y * a1 + w3.z * a2 + w3.w * a3;
            }
            sRed[(0 * 32 + w) * BB + lane] = acc0;
            sRed[(1 * 32 + w) * BB + lane] = acc1;
            sRed[(2 * 32 + w) * BB + lane] = acc2;
            sRed[(3 * 32 + w) * BB + lane] = acc3;
            __syncthreads();
            if (tid < 128) {
                int r = tid >> 5, b = tid & 31;
                float s = 0.f;
#pragma unroll
                for (int i = 0; i < 32; i++) s += sRed[(r * 32 + i) * BB + b];
                g_actX[(r0 + r) * BB + b] = s + rb[r0 + r];
            }
        }
        gridbar();

        // ==== P4: gates + cell (128 blocks x 16 rows'; warp = (4-row group, k-eighth))
        if (blockIdx.x < 128) {
            const int rp0 = blockIdx.x * 16;
            const int rg = w >> 3, q = w & 7;     // rg 0..3 (4-row groups), q 0..7
            float acc0 = 0.f, acc1 = 0.f, acc2 = 0.f, acc3 = 0.f;
            for (int kc = 0; kc < 8; kc++) {
                __syncthreads();
                const float* asrc = (kc < 4) ? (g_actX + kc * 128 * BB)
                                             : (hT_cur + (kc - 4) * 128 * BB);
                ((float4*)sAct)[tid] = ((const float4*)asrc)[tid];
#pragma unroll
                for (int s = 0; s < 2; s++) {
                    int i = tid + s * NTHR;
                    int rl = i >> 7, k = i & 127;
                    int rp = rp0 + rl;
                    int hi = rp >> 2, gate = rp & 3;
                    sW[i] = (kc < 4)
                        ? Wih[(size_t)(gate * HH + hi) * EE + kc * 128 + k]
                        : Whh[(size_t)(gate * HH + hi) * HH + (kc - 4) * 128 + k];
                }
                __syncthreads();
                const int kb = q * 16;    // this warp's 16 K-positions in the chunk
#pragma unroll
                for (int k4 = 0; k4 < 16; k4 += 4) {
                    const float* ap = sAct + (kb + k4) * BB + lane;
                    float a0 = ap[0 * BB], a1 = ap[1 * BB];
                    float a2 = ap[2 * BB], a3 = ap[3 * BB];
                    float4 w0 = *(const float4*)(sW + (rg * 4 + 0) * 128 + kb + k4);
                    float4 w1 = *(const float4*)(sW + (rg * 4 + 1) * 128 + kb + k4);
                    float4 w2 = *(const float4*)(sW + (rg * 4 + 2) * 128 + kb + k4);
                    float4 w3 = *(const float4*)(sW + (rg * 4 + 3) * 128 + kb + k4);
                    acc0 += w0.x * a0 + w0.y * a1 + w0.z * a2 + w0.w * a3;
                    acc1 += w1.x * a0 + w1.y * a1 + w1.z * a2 + w1.w * a3;
                    acc2 += w2.x * a0 + w2.y * a1 + w2.z * a2 + w2.w * a3;
                    acc3 += w3.x * a0 + w3.y * a1 + w3.z * a2 + w3.w * a3;
                }
            }
            sRed[((rg * 4 + 0) * 8 + q) * BB + lane] = acc0;
            sRed[((rg * 4 + 1) * 8 + q) * BB + lane] = acc1;
            sRed[((rg * 4 + 2) * 8 + q) * BB + lane] = acc2;
            sRed[((rg * 4 + 3) * 8 + q) * BB + lane] = acc3;
            __syncthreads();
            if (tid < 512) {
                int rl = tid >> 5, b = tid & 31;
                float s = 0.f;
#pragma unroll
                for (int i = 0; i < 8; i++) s += sRed[(rl * 8 + i) * BB + b];
                sOut[rl * BB + b] = s;
            }
            __syncthreads();
            if (tid < 128) {
                int hl = tid >> 5;
                int b  = tid & 31;
                int hi = blockIdx.x * 4 + hl;
                float iv = sOut[(hl * 4 + 0) * BB + b] + bih[hi]          + bhh[hi];
                float fv = sOut[(hl * 4 + 1) * BB + b] + bih[HH + hi]     + bhh[HH + hi];
                float gv = sOut[(hl * 4 + 2) * BB + b] + bih[2 * HH + hi] + bhh[2 * HH + hi];
                float ov = sOut[(hl * 4 + 3) * BB + b] + bih[3 * HH + hi] + bhh[3 * HH + hi];
                float si = 1.f / (1.f + __expf(-iv));
                float sf = 1.f / (1.f + __expf(-fv));
                float so = 1.f / (1.f + __expf(-ov));
                float c2 = sf * g_cT[hi * BB + b] + si * tanhf(gv);
                float h2 = so * tanhf(c2);
                g_cT[hi * BB + b] = c2;
                hT_nxt[hi * BB + b] = h2;
                h_nxt[b * HH + hi] = h2;
                g_Hall[((size_t)t * BB + b) * HH + hi] = h2;
            }
        }
        gridbar();
    }
}

// ---------------- fp32 -> bf16 hi/lo split ----------------
__device__ __forceinline__ void split_store(float4 v, __nv_bfloat16* H,
                                            __nv_bfloat16* L, size_t off) {
    __nv_bfloat162 h0, h1, l0, l1;
    h0.x = __float2bfloat16(v.x); h0.y = __float2bfloat16(v.y);
    h1.x = __float2bfloat16(v.z); h1.y = __float2bfloat16(v.w);
    l0.x = __float2bfloat16(v.x - __bfloat162float(h0.x));
    l0.y = __float2bfloat16(v.y - __bfloat162float(h0.y));
    l1.x = __float2bfloat16(v.z - __bfloat162float(h1.x));
    l1.y = __float2bfloat16(v.w - __bfloat162float(h1.y));
    *(__nv_bfloat162*)(H + off) = h0; *(__nv_bfloat162*)(H + off + 2) = h1;
    *(__nv_bfloat162*)(L + off) = l0; *(__nv_bfloat162*)(L + off + 2) = l1;
}

__global__ void __launch_bounds__(256) convert_kernel(const float* __restrict__ outW)
{
    const size_t NW4 = ((size_t)VV * EE) / 4;
    const size_t NA4 = ((size_t)SEQ * BB * HH) / 4;
    size_t stride = (size_t)gridDim.x * blockDim.x;
    for (size_t i = (size_t)blockIdx.x * blockDim.x + threadIdx.x;
         i < NW4 + NA4; i += stride) {
        if (i < NW4) {
            float4 v = ((const float4*)outW)[i];
            split_store(v, g_WH, g_WL, i * 4);
        } else {
            size_t j = i - NW4;
            float4 v = ((const float4*)g_Hall)[j];
            split_store(v, g_AH, g_AL, j * 4);
        }
    }
}

// ---------------- tensor-core output GEMM ----------------
#define LDSW 40  // padded smem row stride (bf16 elems)

__device__ __forceinline__ uint32_t s2u(const void* p) {
    return (uint32_t)__cvta_generic_to_shared(p);
}
__device__ __forceinline__ void ldsm_x4(uint32_t r[4], uint32_t addr) {
    asm volatile("ldmatrix.sync.aligned.m8n8.x4.shared.b16 {%0,%1,%2,%3}, [%4];"
                 : "=r"(r[0]), "=r"(r[1]), "=r"(r[2]), "=r"(r[3]) : "r"(addr));
}
__device__ __forceinline__ void mma_bf16(float c[4], const uint32_t a[4], const uint32_t b[2]) {
    asm volatile("mma.sync.aligned.m16n8k16.row.col.f32.bf16.bf16.f32 "
                 "{%0,%1,%2,%3}, {%4,%5,%6,%7}, {%8,%9}, {%0,%1,%2,%3};"
                 : "+f"(c[0]), "+f"(c[1]), "+f"(c[2]), "+f"(c[3])
                 : "r"(a[0]), "r"(a[1]), "r"(a[2]), "r"(a[3]), "r"(b[0]), "r"(b[1]));
}

__global__ void __launch_bounds__(256) out_gemm_tc(
    const float* __restrict__ outb, float* __restrict__ out)
{
    __shared__ __align__(16) __nv_bfloat16 sAH[128 * LDSW];
    __shared__ __align__(16) __nv_bfloat16 sAL[128 * LDSW];
    __shared__ __align__(16) __nv_bfloat16 sBH[128 * LDSW];
    __shared__ __align__(16) __nv_bfloat16 sBL[128 * LDSW];

    const int tid  = threadIdx.x;
    const int lane = tid & 31;
    const int w    = tid >> 5;
    const int wm   = w >> 2;
    const int wn   = w & 3;
    const int m0 = blockIdx.y * 128;
    const int n0 = blockIdx.x * 128;

    float acc[4][4][4];
#pragma unroll
    for (int mt = 0; mt < 4; mt++)
#pragma unroll
        for (int nt = 0; nt < 4; nt++)
#pragma unroll
            for (int r = 0; r < 4; r++) acc[mt][nt][r] = 0.f;

    const int a_row = lane & 15;
    const int a_k8  = (lane >> 4) * 8;
    const int b_nrw = (lane & 7) + ((lane >> 4) << 3);
    const int b_k8  = ((lane >> 3) & 1) * 8;

    const uint32_t uAH = s2u(sAH), uAL = s2u(sAL);
    const uint32_t uBH = s2u(sBH), uBL = s2u(sBL);

    for (int k0 = 0; k0 < 512; k0 += 32) {
        __syncthreads();
#pragma unroll
        for (int i = 0; i < 2; i++) {
            int v = tid + i * 256;
            int row = v >> 2;
            int kc  = (v & 3) * 8;
            size_t ga = (size_t)(m0 + row) * 512 + k0 + kc;
            size_t gb = (size_t)(n0 + row) * 512 + k0 + kc;
            int so = row * LDSW + kc;
            *(uint4*)(sAH + so) = *(const uint4*)(g_AH + ga);
            *(uint4*)(sAL + so) = *(const uint4*)(g_AL + ga);
            *(uint4*)(sBH + so) = *(const uint4*)(g_WH + gb);
            *(uint4*)(sBL + so) = *(const uint4*)(g_WL + gb);
        }
        __syncthreads();

#pragma unroll
        for (int ks = 0; ks < 32; ks += 16) {
            uint32_t aH[4][4], aL[4][4];
#pragma unroll
            for (int mt = 0; mt < 4; mt++) {
                int off = ((wm * 64 + mt * 16 + a_row) * LDSW + ks + a_k8) * 2;
                ldsm_x4(aH[mt], uAH + off);
                ldsm_x4(aL[mt], uAL + off);
            }
            uint32_t bH[4][2], bL[4][2];
#pragma unroll
            for (int p = 0; p < 2; p++) {
                int off = ((wn * 32 + p * 16 + b_nrw) * LDSW + ks + b_k8) * 2;
                uint32_t r[4];
                ldsm_x4(r, uBH + off);
                bH[2 * p][0] = r[0]; bH[2 * p][1] = r[1];
                bH[2 * p + 1][0] = r[2]; bH[2 * p + 1][1] = r[3];
                ldsm_x4(r, uBL + off);
                bL[2 * p][0] = r[0]; bL[2 * p][1] = r[1];
                bL[2 * p + 1][0] = r[2]; bL[2 * p + 1][1] = r[3];
            }
#pragma unroll
            for (int mt = 0; mt < 4; mt++)
#pragma unroll
                for (int nt = 0; nt < 4; nt++) {
                    mma_bf16(acc[mt][nt], aH[mt], bH[nt]);
                    mma_bf16(acc[mt][nt], aH[mt], bL[nt]);
                    mma_bf16(acc[mt][nt], aL[mt], bH[nt]);
                }
        }
    }

#pragma unroll
    for (int mt = 0; mt < 4; mt++) {
#pragma unroll
        for (int half = 0; half < 2; half++) {
            int m = m0 + wm * 64 + mt * 16 + (lane >> 2) + half * 8;
            int tt = m >> 5, b = m & 31;
            float* orow = out + ((size_t)b * SEQ + tt) * VV;
#pragma unroll
            for (int nt = 0; nt < 4; nt++) {
                int n = n0 + wn * 32 + nt * 8 + 2 * (lane & 3);
                float2 bias = *(const float2*)(outb + n);
                float2 v;
                v.x = acc[mt][nt][2 * half + 0] + bias.x;
                v.y = acc[mt][nt][2 * half + 1] + bias.y;
                *(float2*)(orow + n) = v;
            }
        }
    }
}

extern "C" void kernel_launch(void* const* d_in, const int* in_sizes, int n_in,
                              void* d_out, int out_size)
{
    const float* features = (const float*)d_in[0];
    const int*   captions = (const int*)d_in[1];
    const float* embed_W  = (const float*)d_in[2];
    const float* ihW = (const float*)d_in[3];
    const float* ihb = (const float*)d_in[4];
    const float* icW = (const float*)d_in[5];
    const float* icb = (const float*)d_in[6];
    const float* rW  = (const float*)d_in[7];
    const float* rb  = (const float*)d_in[8];
    const float* Wih = (const float*)d_in[9];
    const float* Whh = (const float*)d_in[10];
    const float* bih = (const float*)d_in[11];
    const float* bhh = (const float*)d_in[12];
    const float* outW = (const float*)d_in[13];
    const float* outb = (const float*)d_in[14];

    recurrence_kernel<<<NBLK, NTHR>>>(features, captions, embed_W,
                                      ihW, ihb, icW, icb, rW, rb,
                                      Wih, Whh, bih, bhh);
    convert_kernel<<<2048, 256>>>(outW);
    dim3 grid(VV / 128, (SEQ * BB) / 128);
    out_gemm_tc<<<grid, 256>>>(outb, (float*)d_out);
}

// round 12
// speedup vs baseline: 1.0464x; 1.0464x over previous
#include <cuda_runtime.h>
#include <cuda_bf16.h>
#include <math.h>
#include <stdint.h>

#define BB 32
#define NREG 196
#define EE 512
#define HH 512
#define SEQ 64
#define VV 32000

#define NBLK 148
#define NTHR 512

// ---------------- scratch (device globals; no allocations) ----------------
__device__ float g_fmean[BB * EE];
__device__ __align__(16) float g_hbuf[2][BB * HH];   // [b][k]   (attention)
__device__ __align__(16) float g_hT[2][HH * BB];     // [k][b]   (gate GEMV)
__device__ float g_cT[HH * BB];                      // [k][b]
__device__ __align__(16) float g_actCE[2 * EE * BB]; // [k][b]: k<512 ctx, k>=512 emb*sqrtE
__device__ __align__(16) float g_actX[EE * BB];      // [k][b]: x
__device__ __align__(16) float g_Hall[SEQ * BB * HH];// row (t*32+b)
__device__ unsigned g_bar_count;
__device__ unsigned g_bar_gen;

// bf16 split buffers for tensor-core GEMM
__device__ __align__(16) __nv_bfloat16 g_AH[SEQ * BB * HH];
__device__ __align__(16) __nv_bfloat16 g_AL[SEQ * BB * HH];
__device__ __align__(16) __nv_bfloat16 g_WH[(size_t)VV * EE];
__device__ __align__(16) __nv_bfloat16 g_WL[(size_t)VV * EE];

// ---------------- grid-wide barrier ----------------
__device__ __forceinline__ void gridbar() {
    __syncthreads();
    if (threadIdx.x == 0) {
        unsigned gen = *((volatile unsigned*)&g_bar_gen);
        __threadfence();
        if (atomicAdd(&g_bar_count, 1u) == (unsigned)(gridDim.x - 1)) {
            g_bar_count = 0;
            __threadfence();
            atomicAdd(&g_bar_gen, 1u);
        } else {
            while (*((volatile unsigned*)&g_bar_gen) == gen) { __nanosleep(32); }
        }
        __threadfence();
    }
    __syncthreads();
}

__device__ __forceinline__ float warpsum(float v) {
#pragma unroll
    for (int o = 16; o; o >>= 1) v += __shfl_xor_sync(0xffffffffu, v, o);
    return v;
}

__device__ __forceinline__ float warpdot512(const float* __restrict__ a,
                                            const float* __restrict__ b, int lane) {
    float s = 0.f;
#pragma unroll
    for (int c = 0; c < 4; c++) {
        float4 av = *(const float4*)(a + c * 128 + lane * 4);
        float4 bv = *(const float4*)(b + c * 128 + lane * 4);
        s += av.x * bv.x + av.y * bv.y + av.z * bv.z + av.w * bv.w;
    }
    return s;
}

// ---------------- persistent recurrence kernel ----------------
__global__ void __launch_bounds__(NTHR) recurrence_kernel(
    const float* __restrict__ features, const int* __restrict__ captions,
    const float* __restrict__ embed_W,
    const float* __restrict__ ihW, const float* __restrict__ ihb,
    const float* __restrict__ icW, const float* __restrict__ icb,
    const float* __restrict__ rW,  const float* __restrict__ rb,
    const float* __restrict__ Wih, const float* __restrict__ Whh,
    const float* __restrict__ bih, const float* __restrict__ bhh)
{
    const int tid  = threadIdx.x;
    const int lane = tid & 31;
    const int w    = tid >> 5;
    const int gtid = blockIdx.x * NTHR + tid;
    const int wid_g  = gtid >> 5;
    const int nwarps = (NBLK * NTHR) >> 5;
    const int gstride = NBLK * NTHR;

    __shared__ __align__(16) float sh_h[EE];        // 2 KB
    __shared__ float sSc[NREG];
    __shared__ float sh_attn[NREG];
    __shared__ float sh_red[NTHR / 32];
    __shared__ __align__(16) float sPart[16 * 128]; // 8 KB
    __shared__ __align__(16) float sAct[128 * BB];  // 16 KB
    __shared__ __align__(16) float sW[16 * 128];    // 8 KB
    __shared__ __align__(16) float sRed[16 * 4 * BB]; // 8 KB (P4 partials)
    __shared__ float sOut[16 * BB];                 // 2 KB

    // ---- init a: fmean
    for (int idx = gtid; idx < BB * EE; idx += gstride) {
        int b = idx >> 9, e = idx & 511;
        const float* fp = features + (size_t)b * NREG * EE + e;
        float s = 0.f;
        for (int n = 0; n < NREG; n++) s += fp[n * EE];
        g_fmean[idx] = s * (1.0f / NREG);
    }
    gridbar();

    // ---- init b: h0 / c0 (warp per output)
    for (int task = wid_g; task < 2 * BB * HH; task += nwarps) {
        int which = task & 1;
        int m = task >> 1;
        int b = m >> 9, eo = m & 511;
        const float* Wrow = (which ? icW : ihW) + (size_t)eo * EE;
        float s = warpsum(warpdot512(Wrow, g_fmean + b * EE, lane));
        if (lane == 0) {
            if (which) {
                g_cT[eo * BB + b] = s + icb[eo];
            } else {
                float hv = s + ihb[eo];
                g_hbuf[0][m] = hv;
                g_hT[0][eo * BB + b] = hv;
            }
        }
    }
    gridbar();

    for (int t = 0; t < SEQ; t++) {
        const float* h_cur  = g_hbuf[t & 1];
        const float* hT_cur = g_hT[t & 1];
        float*       h_nxt  = g_hbuf[(t & 1) ^ 1];
        float*       hT_nxt = g_hT[(t & 1) ^ 1];

        // ==== P12 (R10/R8 version): attention, scores redundant per (b,chunk) block
        if (blockIdx.x < 128) {
            const int b = blockIdx.x >> 2;
            const int chunk = blockIdx.x & 3;
            const float* fb = features + (size_t)b * NREG * EE;

            sh_h[tid] = h_cur[b * EE + tid];
            __syncthreads();

            for (int n = w; n < NREG; n += 16) {
                float s = warpsum(warpdot512(fb + (size_t)n * EE, sh_h, lane));
                if (lane == 0) sSc[n] = s;
            }
            __syncthreads();

            float v = (tid < NREG) ? sSc[tid] : -1e30f;
            float m = v;
#pragma unroll
            for (int o = 16; o; o >>= 1) m = fmaxf(m, __shfl_xor_sync(0xffffffffu, m, o));
            if (lane == 0) sh_red[w] = m;
            __syncthreads();
            float mx = sh_red[0];
#pragma unroll
            for (int i = 1; i < 16; i++) mx = fmaxf(mx, sh_red[i]);
            float ev = (tid < NREG) ? __expf(v - mx) : 0.f;
            float ps = warpsum(ev);
            __syncthreads();
            if (lane == 0) sh_red[w] = ps;
            __syncthreads();
            float tot = 0.f;
#pragma unroll
            for (int i = 0; i < 16; i++) tot += sh_red[i];
            if (tid < NREG) sh_attn[tid] = ev / tot;
            __syncthreads();

            float4 cacc = make_float4(0.f, 0.f, 0.f, 0.f);
            const float* fc = fb + chunk * 128 + lane * 4;
#pragma unroll 4
            for (int n = w; n < NREG; n += 16) {
                float a = sh_attn[n];
                float4 fv = *(const float4*)(fc + (size_t)n * EE);
                cacc.x += a * fv.x; cacc.y += a * fv.y;
                cacc.z += a * fv.z; cacc.w += a * fv.w;
            }
            *(float4*)(sPart + w * 128 + lane * 4) = cacc;
            __syncthreads();
            if (tid < 128) {
                float s = 0.f;
#pragma unroll
                for (int i = 0; i < 16; i++) s += sPart[i * 128 + tid];
                g_actCE[(chunk * 128 + tid) * BB + b] = s;
            }
        } else {
            for (int idx = (blockIdx.x - 128) * NTHR + tid; idx < BB * EE;
                 idx += 20 * NTHR) {
                int b = idx >> 9, k = idx & 511;
                int tok = captions[b * SEQ + t];
                g_actCE[(EE + k) * BB + b] =
                    embed_W[(size_t)tok * EE + k] * 22.62741699796952f; // sqrt(512)
            }
        }
        gridbar();

        // ==== P3 (R10 + register prefetch): x = rW @ [ctx; emb] + rb
        if (blockIdx.x < 128) {
            const int r0 = blockIdx.x * 4;
            const int row = w >> 2, q = w & 3;
            const int wr_r = tid >> 7, wr_k = tid & 127;
            float acc = 0.f;

            // preload chunk 0
            float4 pA0 = ((const float4*)g_actCE)[tid];
            float4 pA1 = ((const float4*)g_actCE)[tid + NTHR];
            float  pw  = rW[(size_t)(r0 + wr_r) * (EE + HH) + wr_k];

            for (int kc = 0; kc < 8; kc++) {
                ((float4*)sAct)[tid] = pA0;
                ((float4*)sAct)[tid + NTHR] = pA1;
                sW[tid] = pw;
                __syncthreads();
                if (kc < 7) {
                    const float* asrc = g_actCE + (kc + 1) * 128 * BB;
                    pA0 = ((const float4*)asrc)[tid];
                    pA1 = ((const float4*)asrc)[tid + NTHR];
                    pw  = rW[(size_t)(r0 + wr_r) * (EE + HH) + (kc + 1) * 128 + wr_k];
                }
                const float* wp = sW + row * 128 + q * 32;
#pragma unroll
                for (int k = 0; k < 32; k += 4) {
                    float4 wv = *(const float4*)(wp + k);
                    const float* ap = sAct + (q * 32 + k) * BB + lane;
                    acc += wv.x * ap[0 * BB];
                    acc += wv.y * ap[1 * BB];
                    acc += wv.z * ap[2 * BB];
                    acc += wv.w * ap[3 * BB];
                }
                __syncthreads();
            }
            sOut[(row * 4 + q) * BB + lane] = acc;
            __syncthreads();
            if (tid < 128) {
                int r = tid >> 5, b = tid & 31;
                float s = sOut[(r * 4 + 0) * BB + b] + sOut[(r * 4 + 1) * BB + b]
                        + sOut[(r * 4 + 2) * BB + b] + sOut[(r * 4 + 3) * BB + b];
                g_actX[(r0 + r) * BB + b] = s + rb[r0 + r];
            }
        }
        gridbar();

        // ==== P4 (R10 + register prefetch): gates + cell
        if (blockIdx.x < 128) {
            const int rp0 = blockIdx.x * 16;
            const int rg = w >> 2, qq = w & 3;
            float acc0 = 0.f, acc1 = 0.f, acc2 = 0.f, acc3 = 0.f;

            // weight index components (fixed per thread)
            int wrow[4], wcol[4];
#pragma unroll
            for (int s = 0; s < 4; s++) {
                int i = tid + s * NTHR;
                int rl = i >> 7, k = i & 127;
                int rp = rp0 + rl;
                wrow[s] = (rp & 3) * HH + (rp >> 2);   // gate*HH + hi
                wcol[s] = k;
            }

            // preload chunk 0 (act = g_actX chunk 0, weights = Wih)
            float4 pA0 = ((const float4*)g_actX)[tid];
            float4 pA1 = ((const float4*)g_actX)[tid + NTHR];
            float pw[4];
#pragma unroll
            for (int s = 0; s < 4; s++)
                pw[s] = Wih[(size_t)wrow[s] * EE + wcol[s]];

            for (int kc = 0; kc < 8; kc++) {
                ((float4*)sAct)[tid] = pA0;
                ((float4*)sAct)[tid + NTHR] = pA1;
#pragma unroll
                for (int s = 0; s < 4; s++) sW[tid + s * NTHR] = pw[s];
                __syncthreads();
                if (kc < 7) {
                    int kn = kc + 1;
                    const float* asrc = (kn < 4) ? (g_actX + kn * 128 * BB)
                                                 : (hT_cur + (kn - 4) * 128 * BB);
                    pA0 = ((const float4*)asrc)[tid];
                    pA1 = ((const float4*)asrc)[tid + NTHR];
#pragma unroll
                    for (int s = 0; s < 4; s++)
                        pw[s] = (kn < 4)
                            ? Wih[(size_t)wrow[s] * EE + kn * 128 + wcol[s]]
                            : Whh[(size_t)wrow[s] * HH + (kn - 4) * 128 + wcol[s]];
                }
                const float* w0p = sW + (rg * 4 + 0) * 128 + qq * 32;
                const float* w1p = sW + (rg * 4 + 1) * 128 + qq * 32;
                const float* w2p = sW + (rg * 4 + 2) * 128 + qq * 32;
                const float* w3p = sW + (rg * 4 + 3) * 128 + qq * 32;
#pragma unroll
                for (int k4 = 0; k4 < 32; k4 += 4) {
                    const float* ap = sAct + (qq * 32 + k4) * BB + lane;
                    float a0 = ap[0 * BB], a1 = ap[1 * BB];
                    float a2 = ap[2 * BB], a3 = ap[3 * BB];
                    float4 w0 = *(const float4*)(w0p + k4);
                    float4 w1 = *(const float4*)(w1p + k4);
                    float4 w2 = *(const float4*)(w2p + k4);
                    float4 w3 = *(const float4*)(w3p + k4);
                    acc0 += w0.x * a0 + w0.y * a1 + w0.z * a2 + w0.w * a3;
                    acc1 += w1.x * a0 + w1.y * a1 + w1.z * a2 + w1.w * a3;
                    acc2 += w2.x * a0 + w2.y * a1 + w2.z * a2 + w2.w * a3;
                    acc3 += w3.x * a0 + w3.y * a1 + w3.z * a2 + w3.w * a3;
                }
                __syncthreads();
            }
            sRed[((rg * 4 + 0) * 4 + qq) * BB + lane] = acc0;
            sRed[((rg * 4 + 1) * 4 + qq) * BB + lane] = acc1;
            sRed[((rg * 4 + 2) * 4 + qq) * BB + lane] = acc2;
            sRed[((rg * 4 + 3) * 4 + qq) * BB + lane] = acc3;
            __syncthreads();
            {
                int rl = tid >> 5, b = tid & 31;
                float s = sRed[(rl * 4 + 0) * BB + b] + sRed[(rl * 4 + 1) * BB + b]
                        + sRed[(rl * 4 + 2) * BB + b] + sRed[(rl * 4 + 3) * BB + b];
                sOut[rl * BB + b] = s;
            }
            __syncthreads();
            if (tid < 128) {
                int hl = tid >> 5;
                int b  = tid & 31;
                int hi = blockIdx.x * 4 + hl;
                float iv = sOut[(hl * 4 + 0) * BB + b] + bih[hi]          + bhh[hi];
                float fv = sOut[(hl * 4 + 1) * BB + b] + bih[HH + hi]     + bhh[HH + hi];
                float gv = sOut[(hl * 4 + 2) * BB + b] + bih[2 * HH + hi] + bhh[2 * HH + hi];
                float ov = sOut[(hl * 4 + 3) * BB + b] + bih[3 * HH + hi] + bhh[3 * HH + hi];
                float si = 1.f / (1.f + __expf(-iv));
                float sf = 1.f / (1.f + __expf(-fv));
                float so = 1.f / (1.f + __expf(-ov));
                float c2 = sf * g_cT[hi * BB + b] + si * tanhf(gv);
                float h2 = so * tanhf(c2);
                g_cT[hi * BB + b] = c2;
                hT_nxt[hi * BB + b] = h2;
                h_nxt[b * HH + hi] = h2;
                g_Hall[((size_t)t * BB + b) * HH + hi] = h2;
            }
        }
        gridbar();
    }
}

// ---------------- fp32 -> bf16 hi/lo split ----------------
__device__ __forceinline__ void split_store(float4 v, __nv_bfloat16* H,
                                            __nv_bfloat16* L, size_t off) {
    __nv_bfloat162 h0, h1, l0, l1;
    h0.x = __float2bfloat16(v.x); h0.y = __float2bfloat16(v.y);
    h1.x = __float2bfloat16(v.z); h1.y = __float2bfloat16(v.w);
    l0.x = __float2bfloat16(v.x - __bfloat162float(h0.x));
    l0.y = __float2bfloat16(v.y - __bfloat162float(h0.y));
    l1.x = __float2bfloat16(v.z - __bfloat162float(h1.x));
    l1.y = __float2bfloat16(v.w - __bfloat162float(h1.y));
    *(__nv_bfloat162*)(H + off) = h0; *(__nv_bfloat162*)(H + off + 2) = h1;
    *(__nv_bfloat162*)(L + off) = l0; *(__nv_bfloat162*)(L + off + 2) = l1;
}

__global__ void __launch_bounds__(256) convert_kernel(const float* __restrict__ outW)
{
    const size_t NW4 = ((size_t)VV * EE) / 4;
    const size_t NA4 = ((size_t)SEQ * BB * HH) / 4;
    size_t stride = (size_t)gridDim.x * blockDim.x;
    for (size_t i = (size_t)blockIdx.x * blockDim.x + threadIdx.x;
         i < NW4 + NA4; i += stride) {
        if (i < NW4) {
            float4 v = ((const float4*)outW)[i];
            split_store(v, g_WH, g_WL, i * 4);
        } else {
            size_t j = i - NW4;
            float4 v = ((const float4*)g_Hall)[j];
            split_store(v, g_AH, g_AL, j * 4);
        }
    }
}

// ---------------- tensor-core output GEMM ----------------
#define LDSW 40  // padded smem row stride (bf16 elems)

__device__ __forceinline__ uint32_t s2u(const void* p) {
    return (uint32_t)__cvta_generic_to_shared(p);
}
__device__ __forceinline__ void ldsm_x4(uint32_t r[4], uint32_t addr) {
    asm volatile("ldmatrix.sync.aligned.m8n8.x4.shared.b16 {%0,%1,%2,%3}, [%4];"
                 : "=r"(r[0]), "=r"(r[1]), "=r"(r[2]), "=r"(r[3]) : "r"(addr));
}
__device__ __forceinline__ void mma_bf16(float c[4], const uint32_t a[4], const uint32_t b[2]) {
    asm volatile("mma.sync.aligned.m16n8k16.row.col.f32.bf16.bf16.f32 "
                 "{%0,%1,%2,%3}, {%4,%5,%6,%7}, {%8,%9}, {%0,%1,%2,%3};"
                 : "+f"(c[0]), "+f"(c[1]), "+f"(c[2]), "+f"(c[3])
                 : "r"(a[0]), "r"(a[1]), "r"(a[2]), "r"(a[3]), "r"(b[0]), "r"(b[1]));
}

__global__ void __launch_bounds__(256) out_gemm_tc(
    const float* __restrict__ outb, float* __restrict__ out)
{
    __shared__ __align__(16) __nv_bfloat16 sAH[128 * LDSW];
    __shared__ __align__(16) __nv_bfloat16 sAL[128 * LDSW];
    __shared__ __align__(16) __nv_bfloat16 sBH[128 * LDSW];
    __shared__ __align__(16) __nv_bfloat16 sBL[128 * LDSW];

    const int tid  = threadIdx.x;
    const int lane = tid & 31;
    const int w    = tid >> 5;
    const int wm   = w >> 2;
    const int wn   = w & 3;
    const int m0 = blockIdx.y * 128;
    const int n0 = blockIdx.x * 128;

    float acc[4][4][4];
#pragma unroll
    for (int mt = 0; mt < 4; mt++)
#pragma unroll
        for (int nt = 0; nt < 4; nt++)
#pragma unroll
            for (int r = 0; r < 4; r++) acc[mt][nt][r] = 0.f;

    const int a_row = lane & 15;
    const int a_k8  = (lane >> 4) * 8;
    const int b_nrw = (lane & 7) + ((lane >> 4) << 3);
    const int b_k8  = ((lane >> 3) & 1) * 8;

    const uint32_t uAH = s2u(sAH), uAL = s2u(sAL);
    const uint32_t uBH = s2u(sBH), uBL = s2u(sBL);

    for (int k0 = 0; k0 < 512; k0 += 32) {
        __syncthreads();
#pragma unroll
        for (int i = 0; i < 2; i++) {
            int v = tid + i * 256;
            int row = v >> 2;
            int kc  = (v & 3) * 8;
            size_t ga = (size_t)(m0 + row) * 512 + k0 + kc;
            size_t gb = (size_t)(n0 + row) * 512 + k0 + kc;
            int so = row * LDSW + kc;
            *(uint4*)(sAH + so) = *(const uint4*)(g_AH + ga);
            *(uint4*)(sAL + so) = *(const uint4*)(g_AL + ga);
            *(uint4*)(sBH + so) = *(const uint4*)(g_WH + gb);
            *(uint4*)(sBL + so) = *(const uint4*)(g_WL + gb);
        }
        __syncthreads();

#pragma unroll
        for (int ks = 0; ks < 32; ks += 16) {
            uint32_t aH[4][4], aL[4][4];
#pragma unroll
            for (int mt = 0; mt < 4; mt++) {
                int off = ((wm * 64 + mt * 16 + a_row) * LDSW + ks + a_k8) * 2;
                ldsm_x4(aH[mt], uAH + off);
                ldsm_x4(aL[mt], uAL + off);
            }
            uint32_t bH[4][2], bL[4][2];
#pragma unroll
            for (int p = 0; p < 2; p++) {
                int off = ((wn * 32 + p * 16 + b_nrw) * LDSW + ks + b_k8) * 2;
                uint32_t r[4];
                ldsm_x4(r, uBH + off);
                bH[2 * p][0] = r[0]; bH[2 * p][1] = r[1];
                bH[2 * p + 1][0] = r[2]; bH[2 * p + 1][1] = r[3];
                ldsm_x4(r, uBL + off);
                bL[2 * p][0] = r[0]; bL[2 * p][1] = r[1];
                bL[2 * p + 1][0] = r[2]; bL[2 * p + 1][1] = r[3];
            }
#pragma unroll
            for (int mt = 0; mt < 4; mt++)
#pragma unroll
                for (int nt = 0; nt < 4; nt++) {
                    mma_bf16(acc[mt][nt], aH[mt], bH[nt]);
                    mma_bf16(acc[mt][nt], aH[mt], bL[nt]);
                    mma_bf16(acc[mt][nt], aL[mt], bH[nt]);
                }
        }
    }

#pragma unroll
    for (int mt = 0; mt < 4; mt++) {
#pragma unroll
        for (int half = 0; half < 2; half++) {
            int m = m0 + wm * 64 + mt * 16 + (lane >> 2) + half * 8;
            int tt = m >> 5, b = m & 31;
            float* orow = out + ((size_t)b * SEQ + tt) * VV;
#pragma unroll
            for (int nt = 0; nt < 4; nt++) {
                int n = n0 + wn * 32 + nt * 8 + 2 * (lane & 3);
                float2 bias = *(const float2*)(outb + n);
                float2 v;
                v.x = acc[mt][nt][2 * half + 0] + bias.x;
                v.y = acc[mt][nt][2 * half + 1] + bias.y;
                *(float2*)(orow + n) = v;
            }
        }
    }
}

extern "C" void kernel_launch(void* const* d_in, const int* in_sizes, int n_in,
                              void* d_out, int out_size)
{
    const float* features = (const float*)d_in[0];
    const int*   captions = (const int*)d_in[1];
    const float* embed_W  = (const float*)d_in[2];
    const float* ihW = (const float*)d_in[3];
    const float* ihb = (const float*)d_in[4];
    const float* icW = (const float*)d_in[5];
    const float* icb = (const float*)d_in[6];
    const float* rW  = (const float*)d_in[7];
    const float* rb  = (const float*)d_in[8];
    const float* Wih = (const float*)d_in[9];
    const float* Whh = (const float*)d_in[10];
    const float* bih = (const float*)d_in[11];
    const float* bhh = (const float*)d_in[12];
    const float* outW = (const float*)d_in[13];
    const float* outb = (const float*)d_in[14];

    recurrence_kernel<<<NBLK, NTHR>>>(features, captions, embed_W,
                                      ihW, ihb, icW, icb, rW, rb,
                                      Wih, Whh, bih, bhh);
    convert_kernel<<<2048, 256>>>(outW);
    dim3 grid(VV / 128, (SEQ * BB) / 128);
    out_gemm_tc<<<grid, 256>>>(outb, (float*)d_out);
}

// round 13
// speedup vs baseline: 1.2928x; 1.2354x over previous
#include <cuda_runtime.h>
#include <cuda_bf16.h>
#include <math.h>
#include <stdint.h>

#define BB 32
#define NREG 196
#define EE 512
#define HH 512
#define SEQ 64
#define VV 32000

#define NBLK 148
#define NTHR 512

// ---------------- scratch (device globals; no allocations) ----------------
__device__ float g_fmean[BB * EE];
__device__ __align__(16) float g_hbuf[2][BB * HH];   // [b][k]   (attention)
__device__ __align__(16) float g_hT[2][HH * BB];     // [k][b]   (gate GEMV)
__device__ float g_cT[HH * BB];                      // [k][b]
__device__ __align__(16) float g_actCE[2 * EE * BB]; // [k][b]: k<512 ctx, k>=512 emb*sqrtE
__device__ __align__(16) float g_actX[EE * BB];      // [k][b]: x
__device__ volatile unsigned g_flags[NBLK];          // dist barrier arrival flags
__device__ volatile unsigned g_gen;                  // barrier generation (monotonic)

// bf16 split buffers for tensor-core GEMM (A written directly by recurrence)
__device__ __align__(16) __nv_bfloat16 g_AH[SEQ * BB * HH];
__device__ __align__(16) __nv_bfloat16 g_AL[SEQ * BB * HH];
__device__ __align__(16) __nv_bfloat16 g_WH[(size_t)VV * EE];
__device__ __align__(16) __nv_bfloat16 g_WL[(size_t)VV * EE];

// ---------------- distributed-flag grid barrier ----------------
// Arrival: one STG per block to a distinct address (no atomic serialization).
// Block 0 polls all flags in parallel (one thread per flag), then bumps gen.
// Generations are monotonic -> safe across graph replays.
__device__ __forceinline__ void gridbar() {
    __syncthreads();
    unsigned gen = g_gen;                 // stable between barriers; uniform
    if (threadIdx.x == 0) {
        __threadfence();
        g_flags[blockIdx.x] = gen + 1;    // arrive
    }
    if (blockIdx.x == 0) {
        if (threadIdx.x < NBLK) {
            while (g_flags[threadIdx.x] <= gen) { }
        }
        __syncthreads();
        if (threadIdx.x == 0) {
            __threadfence();
            g_gen = gen + 1;              // release
        }
    } else {
        if (threadIdx.x == 0) {
            while (g_gen == gen) { __nanosleep(32); }
            __threadfence();
        }
    }
    __syncthreads();
}

__device__ __forceinline__ float warpsum(float v) {
#pragma unroll
    for (int o = 16; o; o >>= 1) v += __shfl_xor_sync(0xffffffffu, v, o);
    return v;
}

__device__ __forceinline__ float warpdot512(const float* __restrict__ a,
                                            const float* __restrict__ b, int lane) {
    float s = 0.f;
#pragma unroll
    for (int c = 0; c < 4; c++) {
        float4 av = *(const float4*)(a + c * 128 + lane * 4);
        float4 bv = *(const float4*)(b + c * 128 + lane * 4);
        s += av.x * bv.x + av.y * bv.y + av.z * bv.z + av.w * bv.w;
    }
    return s;
}

// ---------------- persistent recurrence kernel (R10 structure) ----------------
__global__ void __launch_bounds__(NTHR) recurrence_kernel(
    const float* __restrict__ features, const int* __restrict__ captions,
    const float* __restrict__ embed_W,
    const float* __restrict__ ihW, const float* __restrict__ ihb,
    const float* __restrict__ icW, const float* __restrict__ icb,
    const float* __restrict__ rW,  const float* __restrict__ rb,
    const float* __restrict__ Wih, const float* __restrict__ Whh,
    const float* __restrict__ bih, const float* __restrict__ bhh)
{
    const int tid  = threadIdx.x;
    const int lane = tid & 31;
    const int w    = tid >> 5;
    const int gtid = blockIdx.x * NTHR + tid;
    const int wid_g  = gtid >> 5;
    const int nwarps = (NBLK * NTHR) >> 5;
    const int gstride = NBLK * NTHR;

    __shared__ __align__(16) float sh_h[EE];        // 2 KB
    __shared__ float sSc[NREG];
    __shared__ float sh_attn[NREG];
    __shared__ float sh_red[NTHR / 32];
    __shared__ __align__(16) float sPart[16 * 128]; // 8 KB
    __shared__ __align__(16) float sAct[128 * BB];  // 16 KB
    __shared__ __align__(16) float sW[16 * 128];    // 8 KB
    __shared__ __align__(16) float sRed[16 * 4 * BB]; // 8 KB (P4 partials)
    __shared__ float sOut[16 * BB];                 // 2 KB

    // ---- init a: fmean
    for (int idx = gtid; idx < BB * EE; idx += gstride) {
        int b = idx >> 9, e = idx & 511;
        const float* fp = features + (size_t)b * NREG * EE + e;
        float s = 0.f;
        for (int n = 0; n < NREG; n++) s += fp[n * EE];
        g_fmean[idx] = s * (1.0f / NREG);
    }
    gridbar();

    // ---- init b: h0 / c0 (warp per output)
    for (int task = wid_g; task < 2 * BB * HH; task += nwarps) {
        int which = task & 1;
        int m = task >> 1;
        int b = m >> 9, eo = m & 511;
        const float* Wrow = (which ? icW : ihW) + (size_t)eo * EE;
        float s = warpsum(warpdot512(Wrow, g_fmean + b * EE, lane));
        if (lane == 0) {
            if (which) {
                g_cT[eo * BB + b] = s + icb[eo];
            } else {
                float hv = s + ihb[eo];
                g_hbuf[0][m] = hv;
                g_hT[0][eo * BB + b] = hv;
            }
        }
    }
    gridbar();

    for (int t = 0; t < SEQ; t++) {
        const float* h_cur  = g_hbuf[t & 1];
        const float* hT_cur = g_hT[t & 1];
        float*       h_nxt  = g_hbuf[(t & 1) ^ 1];
        float*       hT_nxt = g_hT[(t & 1) ^ 1];

        // ==== P12: attention, scores redundant per (b,chunk) block + emb fill
        if (blockIdx.x < 128) {
            const int b = blockIdx.x >> 2;
            const int chunk = blockIdx.x & 3;
            const float* fb = features + (size_t)b * NREG * EE;

            sh_h[tid] = h_cur[b * EE + tid];
            __syncthreads();

            for (int n = w; n < NREG; n += 16) {
                float s = warpsum(warpdot512(fb + (size_t)n * EE, sh_h, lane));
                if (lane == 0) sSc[n] = s;
            }
            __syncthreads();

            float v = (tid < NREG) ? sSc[tid] : -1e30f;
            float m = v;
#pragma unroll
            for (int o = 16; o; o >>= 1) m = fmaxf(m, __shfl_xor_sync(0xffffffffu, m, o));
            if (lane == 0) sh_red[w] = m;
            __syncthreads();
            float mx = sh_red[0];
#pragma unroll
            for (int i = 1; i < 16; i++) mx = fmaxf(mx, sh_red[i]);
            float ev = (tid < NREG) ? __expf(v - mx) : 0.f;
            float ps = warpsum(ev);
            __syncthreads();
            if (lane == 0) sh_red[w] = ps;
            __syncthreads();
            float tot = 0.f;
#pragma unroll
            for (int i = 0; i < 16; i++) tot += sh_red[i];
            if (tid < NREG) sh_attn[tid] = ev / tot;
            __syncthreads();

            float4 cacc = make_float4(0.f, 0.f, 0.f, 0.f);
            const float* fc = fb + chunk * 128 + lane * 4;
#pragma unroll 4
            for (int n = w; n < NREG; n += 16) {
                float a = sh_attn[n];
                float4 fv = *(const float4*)(fc + (size_t)n * EE);
                cacc.x += a * fv.x; cacc.y += a * fv.y;
                cacc.z += a * fv.z; cacc.w += a * fv.w;
            }
            *(float4*)(sPart + w * 128 + lane * 4) = cacc;
            __syncthreads();
            if (tid < 128) {
                float s = 0.f;
#pragma unroll
                for (int i = 0; i < 16; i++) s += sPart[i * 128 + tid];
                g_actCE[(chunk * 128 + tid) * BB + b] = s;
            }
        } else {
            for (int idx = (blockIdx.x - 128) * NTHR + tid; idx < BB * EE;
                 idx += 20 * NTHR) {
                int b = idx >> 9, k = idx & 511;
                int tok = captions[b * SEQ + t];
                g_actCE[(EE + k) * BB + b] =
                    embed_W[(size_t)tok * EE + k] * 22.62741699796952f; // sqrt(512)
            }
        }
        gridbar();

        // ==== P3: x = rW @ [ctx; emb] + rb  (128 blocks x 4 rows; warp=(row, kq))
        if (blockIdx.x < 128) {
            const int r0 = blockIdx.x * 4;
            const int row = w >> 2, q = w & 3;
            float acc = 0.f;
            for (int kc = 0; kc < 8; kc++) {
                __syncthreads();
                const float* asrc = g_actCE + kc * 128 * BB;
                for (int i4 = tid; i4 < 1024; i4 += NTHR)
                    ((float4*)sAct)[i4] = ((const float4*)asrc)[i4];
                {
                    int r = tid >> 7, k = tid & 127;
                    sW[tid] = rW[(size_t)(r0 + r) * (EE + HH) + kc * 128 + k];
                }
                __syncthreads();
                const float* wp = sW + row * 128 + q * 32;
#pragma unroll
                for (int k = 0; k < 32; k += 4) {
                    float4 wv = *(const float4*)(wp + k);
                    const float* ap = sAct + (q * 32 + k) * BB + lane;
                    acc += wv.x * ap[0 * BB];
                    acc += wv.y * ap[1 * BB];
                    acc += wv.z * ap[2 * BB];
                    acc += wv.w * ap[3 * BB];
                }
            }
            sOut[(row * 4 + q) * BB + lane] = acc;
            __syncthreads();
            if (tid < 128) {
                int r = tid >> 5, b = tid & 31;
                float s = sOut[(r * 4 + 0) * BB + b] + sOut[(r * 4 + 1) * BB + b]
                        + sOut[(r * 4 + 2) * BB + b] + sOut[(r * 4 + 3) * BB + b];
                g_actX[(r0 + r) * BB + b] = s + rb[r0 + r];
            }
        }
        gridbar();

        // ==== P4: gates + cell (128 blocks x 16 rows'; warp = (4-row group, kq))
        if (blockIdx.x < 128) {
            const int rp0 = blockIdx.x * 16;
            const int rg = w >> 2, qq = w & 3;
            float acc0 = 0.f, acc1 = 0.f, acc2 = 0.f, acc3 = 0.f;
            for (int kc = 0; kc < 8; kc++) {
                __syncthreads();
                const float* asrc = (kc < 4) ? (g_actX + kc * 128 * BB)
                                             : (hT_cur + (kc - 4) * 128 * BB);
                for (int i4 = tid; i4 < 1024; i4 += NTHR)
                    ((float4*)sAct)[i4] = ((const float4*)asrc)[i4];
#pragma unroll
                for (int s = 0; s < 4; s++) {
                    int i = tid + s * NTHR;
                    int rl = i >> 7, k = i & 127;
                    int rp = rp0 + rl;
                    int hi = rp >> 2, gate = rp & 3;
                    sW[i] = (kc < 4)
                        ? Wih[(size_t)(gate * HH + hi) * EE + kc * 128 + k]
                        : Whh[(size_t)(gate * HH + hi) * HH + (kc - 4) * 128 + k];
                }
                __syncthreads();
                const float* w0p = sW + (rg * 4 + 0) * 128 + qq * 32;
                const float* w1p = sW + (rg * 4 + 1) * 128 + qq * 32;
                const float* w2p = sW + (rg * 4 + 2) * 128 + qq * 32;
                const float* w3p = sW + (rg * 4 + 3) * 128 + qq * 32;
#pragma unroll
                for (int k4 = 0; k4 < 32; k4 += 4) {
                    const float* ap = sAct + (qq * 32 + k4) * BB + lane;
                    float a0 = ap[0 * BB], a1 = ap[1 * BB];
                    float a2 = ap[2 * BB], a3 = ap[3 * BB];
                    float4 w0 = *(const float4*)(w0p + k4);
                    float4 w1 = *(const float4*)(w1p + k4);
                    float4 w2 = *(const float4*)(w2p + k4);
                    float4 w3 = *(const float4*)(w3p + k4);
                    acc0 += w0.x * a0 + w0.y * a1 + w0.z * a2 + w0.w * a3;
                    acc1 += w1.x * a0 + w1.y * a1 + w1.z * a2 + w1.w * a3;
                    acc2 += w2.x * a0 + w2.y * a1 + w2.z * a2 + w2.w * a3;
                    acc3 += w3.x * a0 + w3.y * a1 + w3.z * a2 + w3.w * a3;
                }
            }
            sRed[((rg * 4 + 0) * 4 + qq) * BB + lane] = acc0;
            sRed[((rg * 4 + 1) * 4 + qq) * BB + lane] = acc1;
            sRed[((rg * 4 + 2) * 4 + qq) * BB + lane] = acc2;
            sRed[((rg * 4 + 3) * 4 + qq) * BB + lane] = acc3;
            __syncthreads();
            {
                int rl = tid >> 5, b = tid & 31;
                float s = sRed[(rl * 4 + 0) * BB + b] + sRed[(rl * 4 + 1) * BB + b]
                        + sRed[(rl * 4 + 2) * BB + b] + sRed[(rl * 4 + 3) * BB + b];
                sOut[rl * BB + b] = s;
            }
            __syncthreads();
            if (tid < 128) {
                int hl = tid >> 5;
                int b  = tid & 31;
                int hi = blockIdx.x * 4 + hl;
                float iv = sOut[(hl * 4 + 0) * BB + b] + bih[hi]          + bhh[hi];
                float fv = sOut[(hl * 4 + 1) * BB + b] + bih[HH + hi]     + bhh[HH + hi];
                float gv = sOut[(hl * 4 + 2) * BB + b] + bih[2 * HH + hi] + bhh[2 * HH + hi];
                float ov = sOut[(hl * 4 + 3) * BB + b] + bih[3 * HH + hi] + bhh[3 * HH + hi];
                float si = 1.f / (1.f + __expf(-iv));
                float sf = 1.f / (1.f + __expf(-fv));
                float so = 1.f / (1.f + __expf(-ov));
                float c2 = sf * g_cT[hi * BB + b] + si * tanhf(gv);
                float h2 = so * tanhf(c2);
                g_cT[hi * BB + b] = c2;
                hT_nxt[hi * BB + b] = h2;
                h_nxt[b * HH + hi] = h2;
                // write bf16 hi/lo split of h2 directly (feeds out_gemm_tc)
                size_t ai = ((size_t)t * BB + b) * HH + hi;
                __nv_bfloat16 hh = __float2bfloat16(h2);
                g_AH[ai] = hh;
                g_AL[ai] = __float2bfloat16(h2 - __bfloat162float(hh));
            }
        }
        gridbar();
    }
}

// ---------------- fp32 -> bf16 hi/lo split (outW only) ----------------
__device__ __forceinline__ void split_store(float4 v, __nv_bfloat16* H,
                                            __nv_bfloat16* L, size_t off) {
    __nv_bfloat162 h0, h1, l0, l1;
    h0.x = __float2bfloat16(v.x); h0.y = __float2bfloat16(v.y);
    h1.x = __float2bfloat16(v.z); h1.y = __float2bfloat16(v.w);
    l0.x = __float2bfloat16(v.x - __bfloat162float(h0.x));
    l0.y = __float2bfloat16(v.y - __bfloat162float(h0.y));
    l1.x = __float2bfloat16(v.z - __bfloat162float(h1.x));
    l1.y = __float2bfloat16(v.w - __bfloat162float(h1.y));
    *(__nv_bfloat162*)(H + off) = h0; *(__nv_bfloat162*)(H + off + 2) = h1;
    *(__nv_bfloat162*)(L + off) = l0; *(__nv_bfloat162*)(L + off + 2) = l1;
}

__global__ void __launch_bounds__(256) convert_kernel(const float* __restrict__ outW)
{
    const size_t NW4 = ((size_t)VV * EE) / 4;
    size_t stride = (size_t)gridDim.x * blockDim.x;
    for (size_t i = (size_t)blockIdx.x * blockDim.x + threadIdx.x;
         i < NW4; i += stride) {
        float4 v = ((const float4*)outW)[i];
        split_store(v, g_WH, g_WL, i * 4);
    }
}

// ---------------- tensor-core output GEMM ----------------
#define LDSW 40  // padded smem row stride (bf16 elems)

__device__ __forceinline__ uint32_t s2u(const void* p) {
    return (uint32_t)__cvta_generic_to_shared(p);
}
__device__ __forceinline__ void ldsm_x4(uint32_t r[4], uint32_t addr) {
    asm volatile("ldmatrix.sync.aligned.m8n8.x4.shared.b16 {%0,%1,%2,%3}, [%4];"
                 : "=r"(r[0]), "=r"(r[1]), "=r"(r[2]), "=r"(r[3]) : "r"(addr));
}
__device__ __forceinline__ void mma_bf16(float c[4], const uint32_t a[4], const uint32_t b[2]) {
    asm volatile("mma.sync.aligned.m16n8k16.row.col.f32.bf16.bf16.f32 "
                 "{%0,%1,%2,%3}, {%4,%5,%6,%7}, {%8,%9}, {%0,%1,%2,%3};"
                 : "+f"(c[0]), "+f"(c[1]), "+f"(c[2]), "+f"(c[3])
                 : "r"(a[0]), "r"(a[1]), "r"(a[2]), "r"(a[3]), "r"(b[0]), "r"(b[1]));
}

__global__ void __launch_bounds__(256) out_gemm_tc(
    const float* __restrict__ outb, float* __restrict__ out)
{
    __shared__ __align__(16) __nv_bfloat16 sAH[128 * LDSW];
    __shared__ __align__(16) __nv_bfloat16 sAL[128 * LDSW];
    __shared__ __align__(16) __nv_bfloat16 sBH[128 * LDSW];
    __shared__ __align__(16) __nv_bfloat16 sBL[128 * LDSW];

    const int tid  = threadIdx.x;
    const int lane = tid & 31;
    const int w    = tid >> 5;
    const int wm   = w >> 2;
    const int wn   = w & 3;
    const int m0 = blockIdx.y * 128;
    const int n0 = blockIdx.x * 128;

    float acc[4][4][4];
#pragma unroll
    for (int mt = 0; mt < 4; mt++)
#pragma unroll
        for (int nt = 0; nt < 4; nt++)
#pragma unroll
            for (int r = 0; r < 4; r++) acc[mt][nt][r] = 0.f;

    const int a_row = lane & 15;
    const int a_k8  = (lane >> 4) * 8;
    const int b_nrw = (lane & 7) + ((lane >> 4) << 3);
    const int b_k8  = ((lane >> 3) & 1) * 8;

    const uint32_t uAH = s2u(sAH), uAL = s2u(sAL);
    const uint32_t uBH = s2u(sBH), uBL = s2u(sBL);

    for (int k0 = 0; k0 < 512; k0 += 32) {
        __syncthreads();
#pragma unroll
        for (int i = 0; i < 2; i++) {
            int v = tid + i * 256;
            int row = v >> 2;
            int kc  = (v & 3) * 8;
            size_t ga = (size_t)(m0 + row) * 512 + k0 + kc;
            size_t gb = (size_t)(n0 + row) * 512 + k0 + kc;
            int so = row * LDSW + kc;
            *(uint4*)(sAH + so) = *(const uint4*)(g_AH + ga);
            *(uint4*)(sAL + so) = *(const uint4*)(g_AL + ga);
            *(uint4*)(sBH + so) = *(const uint4*)(g_WH + gb);
            *(uint4*)(sBL + so) = *(const uint4*)(g_WL + gb);
        }
        __syncthreads();

#pragma unroll
        for (int ks = 0; ks < 32; ks += 16) {
            uint32_t aH[4][4], aL[4][4];
#pragma unroll
            for (int mt = 0; mt < 4; mt++) {
                int off = ((wm * 64 + mt * 16 + a_row) * LDSW + ks + a_k8) * 2;
                ldsm_x4(aH[mt], uAH + off);
                ldsm_x4(aL[mt], uAL + off);
            }
            uint32_t bH[4][2], bL[4][2];
#pragma unroll
            for (int p = 0; p < 2; p++) {
                int off = ((wn * 32 + p * 16 + b_nrw) * LDSW + ks + b_k8) * 2;
                uint32_t r[4];
                ldsm_x4(r, uBH + off);
                bH[2 * p][0] = r[0]; bH[2 * p][1] = r[1];
                bH[2 * p + 1][0] = r[2]; bH[2 * p + 1][1] = r[3];
                ldsm_x4(r, uBL + off);
                bL[2 * p][0] = r[0]; bL[2 * p][1] = r[1];
                bL[2 * p + 1][0] = r[2]; bL[2 * p + 1][1] = r[3];
            }
#pragma unroll
            for (int mt = 0; mt < 4; mt++)
#pragma unroll
                for (int nt = 0; nt < 4; nt++) {
                    mma_bf16(acc[mt][nt], aH[mt], bH[nt]);
                    mma_bf16(acc[mt][nt], aH[mt], bL[nt]);
                    mma_bf16(acc[mt][nt], aL[mt], bH[nt]);
                }
        }
    }

#pragma unroll
    for (int mt = 0; mt < 4; mt++) {
#pragma unroll
        for (int half = 0; half < 2; half++) {
            int m = m0 + wm * 64 + mt * 16 + (lane >> 2) + half * 8;
            int tt = m >> 5, b = m & 31;
            float* orow = out + ((size_t)b * SEQ + tt) * VV;
#pragma unroll
            for (int nt = 0; nt < 4; nt++) {
                int n = n0 + wn * 32 + nt * 8 + 2 * (lane & 3);
                float2 bias = *(const float2*)(outb + n);
                float2 v;
                v.x = acc[mt][nt][2 * half + 0] + bias.x;
                v.y = acc[mt][nt][2 * half + 1] + bias.y;
                *(float2*)(orow + n) = v;
            }
        }
    }
}

extern "C" void kernel_launch(void* const* d_in, const int* in_sizes, int n_in,
                              void* d_out, int out_size)
{
    const float* features = (const float*)d_in[0];
    const int*   captions = (const int*)d_in[1];
    const float* embed_W  = (const float*)d_in[2];
    const float* ihW = (const float*)d_in[3];
    const float* ihb = (const float*)d_in[4];
    const float* icW = (const float*)d_in[5];
    const float* icb = (const float*)d_in[6];
    const float* rW  = (const float*)d_in[7];
    const float* rb  = (const float*)d_in[8];
    const float* Wih = (const float*)d_in[9];
    const float* Whh = (const float*)d_in[10];
    const float* bih = (const float*)d_in[11];
    const float* bhh = (const float*)d_in[12];
    const float* outW = (const float*)d_in[13];
    const float* outb = (const float*)d_in[14];

    recurrence_kernel<<<NBLK, NTHR>>>(features, captions, embed_W,
                                      ihW, ihb, icW, icb, rW, rb,
                                      Wih, Whh, bih, bhh);
    convert_kernel<<<2048, 256>>>(outW);
    dim3 grid(VV / 128, (SEQ * BB) / 128);
    out_gemm_tc<<<grid, 256>>>(outb, (float*)d_out);
}

// round 14
// speedup vs baseline: 1.4566x; 1.1267x over previous
#include <cuda_runtime.h>
#include <cuda_bf16.h>
#include <math.h>
#include <stdint.h>

#define BB 32
#define NREG 196
#define EE 512
#define HH 512
#define SEQ 64
#define VV 32000

#define NBLK 148
#define NTHR 512

// ---------------- scratch (device globals; no allocations) ----------------
__device__ float g_fmean[BB * EE];
__device__ __align__(16) float g_hbuf[2][BB * HH];   // [b][k]   (attention)
__device__ __align__(16) float g_hT[2][HH * BB];     // [k][b]   (gate GEMV)
__device__ float g_cT[HH * BB];                      // [k][b]
__device__ __align__(16) float g_actCE[2 * EE * BB]; // [k][b]: k<512 ctx, k>=512 emb*sqrtE
__device__ __align__(16) float g_Hall[SEQ * BB * HH];// row (t*32+b)
__device__ __align__(16) float g_Wf[4 * HH * (EE + HH)]; // fused Wih@rW, rows in rp order (8MB)
__device__ float g_bf[4 * HH];                       // fused bias (orig gate-row indexing)
__device__ unsigned g_bar_count;
__device__ unsigned g_bar_gen;

// bf16 split buffers for tensor-core GEMM
__device__ __align__(16) __nv_bfloat16 g_AH[SEQ * BB * HH];
__device__ __align__(16) __nv_bfloat16 g_AL[SEQ * BB * HH];
__device__ __align__(16) __nv_bfloat16 g_WH[(size_t)VV * EE];
__device__ __align__(16) __nv_bfloat16 g_WL[(size_t)VV * EE];

// ---------------- grid-wide barrier (R10 version) ----------------
__device__ __forceinline__ void gridbar() {
    __syncthreads();
    if (threadIdx.x == 0) {
        unsigned gen = *((volatile unsigned*)&g_bar_gen);
        __threadfence();
        if (atomicAdd(&g_bar_count, 1u) == (unsigned)(gridDim.x - 1)) {
            g_bar_count = 0;
            __threadfence();
            atomicAdd(&g_bar_gen, 1u);
        } else {
            while (*((volatile unsigned*)&g_bar_gen) == gen) { __nanosleep(32); }
        }
        __threadfence();
    }
    __syncthreads();
}

__device__ __forceinline__ float warpsum(float v) {
#pragma unroll
    for (int o = 16; o; o >>= 1) v += __shfl_xor_sync(0xffffffffu, v, o);
    return v;
}

__device__ __forceinline__ float warpdot512(const float* __restrict__ a,
                                            const float* __restrict__ b, int lane) {
    float s = 0.f;
#pragma unroll
    for (int c = 0; c < 4; c++) {
        float4 av = *(const float4*)(a + c * 128 + lane * 4);
        float4 bv = *(const float4*)(b + c * 128 + lane * 4);
        s += av.x * bv.x + av.y * bv.y + av.z * bv.z + av.w * bv.w;
    }
    return s;
}

// ---------------- precompute: Wf = Wih @ rW (rows permuted to rp order) ----------------
// rp row m maps to Wih row (m&3)*HH + (m>>2).  C[2048x1024] = Aperm[2048x512] @ rW[512x1024]
__global__ void __launch_bounds__(256) pre_wf(const float* __restrict__ Wih,
                                              const float* __restrict__ rW)
{
    __shared__ __align__(16) float As[16][128];
    __shared__ __align__(16) float Bs[16][128];
    const int bn = blockIdx.x;          // 0..7
    const int bm = blockIdx.y;          // 0..15
    const int tid = threadIdx.x;
    const int tx = tid & 15, ty = tid >> 4;

    float acc[8][8];
#pragma unroll
    for (int i = 0; i < 8; i++)
#pragma unroll
        for (int j = 0; j < 8; j++) acc[i][j] = 0.f;

    for (int k0 = 0; k0 < 512; k0 += 16) {
#pragma unroll
        for (int i = 0; i < 2; i++) {
            int f = tid + i * 256;
            // A tile: 128 rows x 16 k
            int row = f >> 2;
            int cg  = (f & 3) * 4;
            int m = bm * 128 + row;
            int arow = (m & 3) * HH + (m >> 2);
            float4 va = *(const float4*)(Wih + (size_t)arow * EE + k0 + cg);
            As[cg + 0][row] = va.x; As[cg + 1][row] = va.y;
            As[cg + 2][row] = va.z; As[cg + 3][row] = va.w;
            // B tile: 16 k x 128 n
            int kk = f >> 5;
            int n4 = (f & 31) * 4;
            float4 vb = *(const float4*)(rW + (size_t)(k0 + kk) * (EE + HH) + bn * 128 + n4);
            *(float4*)&Bs[kk][n4] = vb;
        }
        __syncthreads();
#pragma unroll
        for (int kk = 0; kk < 16; kk++) {
            float a[8], b[8];
#pragma unroll
            for (int i = 0; i < 8; i += 4) {
                float4 v = *(const float4*)&As[kk][ty * 8 + i];
                a[i] = v.x; a[i + 1] = v.y; a[i + 2] = v.z; a[i + 3] = v.w;
            }
#pragma unroll
            for (int j = 0; j < 8; j += 4) {
                float4 v = *(const float4*)&Bs[kk][tx * 8 + j];
                b[j] = v.x; b[j + 1] = v.y; b[j + 2] = v.z; b[j + 3] = v.w;
            }
#pragma unroll
            for (int i = 0; i < 8; i++)
#pragma unroll
                for (int j = 0; j < 8; j++) acc[i][j] += a[i] * b[j];
        }
        __syncthreads();
    }
#pragma unroll
    for (int i = 0; i < 8; i++) {
        int m = bm * 128 + ty * 8 + i;
        float* crow = g_Wf + (size_t)m * (EE + HH) + bn * 128 + tx * 8;
#pragma unroll
        for (int j = 0; j < 8; j += 4) {
            float4 v;
            v.x = acc[i][j]; v.y = acc[i][j + 1]; v.z = acc[i][j + 2]; v.w = acc[i][j + 3];
            *(float4*)(crow + j) = v;
        }
    }
}

// bf[r] = bih[r] + bhh[r] + Wih_row_r . rb   (original gate-row indexing)
__global__ void __launch_bounds__(256) pre_bias(const float* __restrict__ Wih,
                                                const float* __restrict__ rb,
                                                const float* __restrict__ bih,
                                                const float* __restrict__ bhh)
{
    int lane = threadIdx.x & 31;
    int wid_g = (blockIdx.x * 256 + threadIdx.x) >> 5;
    int nw = (gridDim.x * 256) >> 5;
    for (int r = wid_g; r < 4 * HH; r += nw) {
        float s = warpsum(warpdot512(Wih + (size_t)r * EE, rb, lane));
        if (lane == 0) g_bf[r] = s + bih[r] + bhh[r];
    }
}

// ---------------- persistent recurrence kernel (2 barriers/step) ----------------
__global__ void __launch_bounds__(NTHR) recurrence_kernel(
    const float* __restrict__ features, const int* __restrict__ captions,
    const float* __restrict__ embed_W,
    const float* __restrict__ ihW, const float* __restrict__ ihb,
    const float* __restrict__ icW, const float* __restrict__ icb,
    const float* __restrict__ Whh)
{
    const int tid  = threadIdx.x;
    const int lane = tid & 31;
    const int w    = tid >> 5;
    const int gtid = blockIdx.x * NTHR + tid;
    const int wid_g  = gtid >> 5;
    const int nwarps = (NBLK * NTHR) >> 5;
    const int gstride = NBLK * NTHR;

    __shared__ __align__(16) float sh_h[EE];        // 2 KB
    __shared__ float sSc[NREG];
    __shared__ float sh_attn[NREG];
    __shared__ float sh_red[NTHR / 32];
    __shared__ __align__(16) float sPart[16 * 128]; // 8 KB
    __shared__ __align__(16) float sAct[128 * BB];  // 16 KB
    __shared__ __align__(16) float sW[16 * 128];    // 8 KB
    __shared__ __align__(16) float sRed[16 * 4 * BB]; // 8 KB
    __shared__ float sOut[16 * BB];                 // 2 KB

    // ---- init a: fmean
    for (int idx = gtid; idx < BB * EE; idx += gstride) {
        int b = idx >> 9, e = idx & 511;
        const float* fp = features + (size_t)b * NREG * EE + e;
        float s = 0.f;
        for (int n = 0; n < NREG; n++) s += fp[n * EE];
        g_fmean[idx] = s * (1.0f / NREG);
    }
    gridbar();

    // ---- init b: h0 / c0 (warp per output)
    for (int task = wid_g; task < 2 * BB * HH; task += nwarps) {
        int which = task & 1;
        int m = task >> 1;
        int b = m >> 9, eo = m & 511;
        const float* Wrow = (which ? icW : ihW) + (size_t)eo * EE;
        float s = warpsum(warpdot512(Wrow, g_fmean + b * EE, lane));
        if (lane == 0) {
            if (which) {
                g_cT[eo * BB + b] = s + icb[eo];
            } else {
                float hv = s + ihb[eo];
                g_hbuf[0][m] = hv;
                g_hT[0][eo * BB + b] = hv;
            }
        }
    }
    gridbar();

    for (int t = 0; t < SEQ; t++) {
        const float* h_cur  = g_hbuf[t & 1];
        const float* hT_cur = g_hT[t & 1];
        float*       h_nxt  = g_hbuf[(t & 1) ^ 1];
        float*       hT_nxt = g_hT[(t & 1) ^ 1];

        // ==== P12: attention (scores redundant per (b,chunk) block) + emb fill
        if (blockIdx.x < 128) {
            const int b = blockIdx.x >> 2;
            const int chunk = blockIdx.x & 3;
            const float* fb = features + (size_t)b * NREG * EE;

            sh_h[tid] = h_cur[b * EE + tid];
            __syncthreads();

            for (int n = w; n < NREG; n += 16) {
                float s = warpsum(warpdot512(fb + (size_t)n * EE, sh_h, lane));
                if (lane == 0) sSc[n] = s;
            }
            __syncthreads();

            float v = (tid < NREG) ? sSc[tid] : -1e30f;
            float m = v;
#pragma unroll
            for (int o = 16; o; o >>= 1) m = fmaxf(m, __shfl_xor_sync(0xffffffffu, m, o));
            if (lane == 0) sh_red[w] = m;
            __syncthreads();
            float mx = sh_red[0];
#pragma unroll
            for (int i = 1; i < 16; i++) mx = fmaxf(mx, sh_red[i]);
            float ev = (tid < NREG) ? __expf(v - mx) : 0.f;
            float ps = warpsum(ev);
            __syncthreads();
            if (lane == 0) sh_red[w] = ps;
            __syncthreads();
            float tot = 0.f;
#pragma unroll
            for (int i = 0; i < 16; i++) tot += sh_red[i];
            if (tid < NREG) sh_attn[tid] = ev / tot;
            __syncthreads();

            float4 cacc = make_float4(0.f, 0.f, 0.f, 0.f);
            const float* fc = fb + chunk * 128 + lane * 4;
#pragma unroll 4
            for (int n = w; n < NREG; n += 16) {
                float a = sh_attn[n];
                float4 fv = *(const float4*)(fc + (size_t)n * EE);
                cacc.x += a * fv.x; cacc.y += a * fv.y;
                cacc.z += a * fv.z; cacc.w += a * fv.w;
            }
            *(float4*)(sPart + w * 128 + lane * 4) = cacc;
            __syncthreads();
            if (tid < 128) {
                float s = 0.f;
#pragma unroll
                for (int i = 0; i < 16; i++) s += sPart[i * 128 + tid];
                g_actCE[(chunk * 128 + tid) * BB + b] = s;
            }
        } else {
            for (int idx = (blockIdx.x - 128) * NTHR + tid; idx < BB * EE;
                 idx += 20 * NTHR) {
                int b = idx >> 9, k = idx & 511;
                int tok = captions[b * SEQ + t];
                g_actCE[(EE + k) * BB + b] =
                    embed_W[(size_t)tok * EE + k] * 22.62741699796952f; // sqrt(512)
            }
        }
        gridbar();

        // ==== P4': fused gates + cell. K = 1536 (ctx|emb via Wf, h via Whh)
        if (blockIdx.x < 128) {
            const int rp0 = blockIdx.x * 16;
            const int rg = w >> 2, qq = w & 3;
            float acc0 = 0.f, acc1 = 0.f, acc2 = 0.f, acc3 = 0.f;
            for (int kc = 0; kc < 12; kc++) {
                __syncthreads();
                const float* asrc = (kc < 8) ? (g_actCE + kc * 128 * BB)
                                             : (hT_cur + (kc - 8) * 128 * BB);
                for (int i4 = tid; i4 < 1024; i4 += NTHR)
                    ((float4*)sAct)[i4] = ((const float4*)asrc)[i4];
#pragma unroll
                for (int s = 0; s < 4; s++) {
                    int i = tid + s * NTHR;
                    int rl = i >> 7, k = i & 127;
                    if (kc < 8) {
                        sW[i] = g_Wf[(size_t)(rp0 + rl) * (EE + HH) + kc * 128 + k];
                    } else {
                        int rp = rp0 + rl;
                        int hi = rp >> 2, gate = rp & 3;
                        sW[i] = Whh[(size_t)(gate * HH + hi) * HH + (kc - 8) * 128 + k];
                    }
                }
                __syncthreads();
                const float* w0p = sW + (rg * 4 + 0) * 128 + qq * 32;
                const float* w1p = sW + (rg * 4 + 1) * 128 + qq * 32;
                const float* w2p = sW + (rg * 4 + 2) * 128 + qq * 32;
                const float* w3p = sW + (rg * 4 + 3) * 128 + qq * 32;
#pragma unroll
                for (int k4 = 0; k4 < 32; k4 += 4) {
                    const float* ap = sAct + (qq * 32 + k4) * BB + lane;
                    float a0 = ap[0 * BB], a1 = ap[1 * BB];
                    float a2 = ap[2 * BB], a3 = ap[3 * BB];
                    float4 w0 = *(const float4*)(w0p + k4);
                    float4 w1 = *(const float4*)(w1p + k4);
                    float4 w2 = *(const float4*)(w2p + k4);
                    float4 w3 = *(const float4*)(w3p + k4);
                    acc0 += w0.x * a0 + w0.y * a1 + w0.z * a2 + w0.w * a3;
                    acc1 += w1.x * a0 + w1.y * a1 + w1.z * a2 + w1.w * a3;
                    acc2 += w2.x * a0 + w2.y * a1 + w2.z * a2 + w2.w * a3;
                    acc3 += w3.x * a0 + w3.y * a1 + w3.z * a2 + w3.w * a3;
                }
            }
            sRed[((rg * 4 + 0) * 4 + qq) * BB + lane] = acc0;
            sRed[((rg * 4 + 1) * 4 + qq) * BB + lane] = acc1;
            sRed[((rg * 4 + 2) * 4 + qq) * BB + lane] = acc2;
            sRed[((rg * 4 + 3) * 4 + qq) * BB + lane] = acc3;
            __syncthreads();
            {
                int rl = tid >> 5, b = tid & 31;
                float s = sRed[(rl * 4 + 0) * BB + b] + sRed[(rl * 4 + 1) * BB + b]
                        + sRed[(rl * 4 + 2) * BB + b] + sRed[(rl * 4 + 3) * BB + b];
                sOut[rl * BB + b] = s;
            }
            __syncthreads();
            if (tid < 128) {
                int hl = tid >> 5;
                int b  = tid & 31;
                int hi = blockIdx.x * 4 + hl;
                float iv = sOut[(hl * 4 + 0) * BB + b] + g_bf[hi];
                float fv = sOut[(hl * 4 + 1) * BB + b] + g_bf[HH + hi];
                float gv = sOut[(hl * 4 + 2) * BB + b] + g_bf[2 * HH + hi];
                float ov = sOut[(hl * 4 + 3) * BB + b] + g_bf[3 * HH + hi];
                float si = 1.f / (1.f + __expf(-iv));
                float sf = 1.f / (1.f + __expf(-fv));
                float so = 1.f / (1.f + __expf(-ov));
                float c2 = sf * g_cT[hi * BB + b] + si * tanhf(gv);
                float h2 = so * tanhf(c2);
                g_cT[hi * BB + b] = c2;
                hT_nxt[hi * BB + b] = h2;
                h_nxt[b * HH + hi] = h2;
                g_Hall[((size_t)t * BB + b) * HH + hi] = h2;
            }
        }
        gridbar();
    }
}

// ---------------- fp32 -> bf16 hi/lo split ----------------
__device__ __forceinline__ void split_store(float4 v, __nv_bfloat16* H,
                                            __nv_bfloat16* L, size_t off) {
    __nv_bfloat162 h0, h1, l0, l1;
    h0.x = __float2bfloat16(v.x); h0.y = __float2bfloat16(v.y);
    h1.x = __float2bfloat16(v.z); h1.y = __float2bfloat16(v.w);
    l0.x = __float2bfloat16(v.x - __bfloat162float(h0.x));
    l0.y = __float2bfloat16(v.y - __bfloat162float(h0.y));
    l1.x = __float2bfloat16(v.z - __bfloat162float(h1.x));
    l1.y = __float2bfloat16(v.w - __bfloat162float(h1.y));
    *(__nv_bfloat162*)(H + off) = h0; *(__nv_bfloat162*)(H + off + 2) = h1;
    *(__nv_bfloat162*)(L + off) = l0; *(__nv_bfloat162*)(L + off + 2) = l1;
}

__global__ void __launch_bounds__(256) convert_kernel(const float* __restrict__ outW)
{
    const size_t NW4 = ((size_t)VV * EE) / 4;
    const size_t NA4 = ((size_t)SEQ * BB * HH) / 4;
    size_t stride = (size_t)gridDim.x * blockDim.x;
    for (size_t i = (size_t)blockIdx.x * blockDim.x + threadIdx.x;
         i < NW4 + NA4; i += stride) {
        if (i < NW4) {
            float4 v = ((const float4*)outW)[i];
            split_store(v, g_WH, g_WL, i * 4);
        } else {
            size_t j = i - NW4;
            float4 v = ((const float4*)g_Hall)[j];
            split_store(v, g_AH, g_AL, j * 4);
        }
    }
}

// ---------------- tensor-core output GEMM ----------------
#define LDSW 40  // padded smem row stride (bf16 elems)

__device__ __forceinline__ uint32_t s2u(const void* p) {
    return (uint32_t)__cvta_generic_to_shared(p);
}
__device__ __forceinline__ void ldsm_x4(uint32_t r[4], uint32_t addr) {
    asm volatile("ldmatrix.sync.aligned.m8n8.x4.shared.b16 {%0,%1,%2,%3}, [%4];"
                 : "=r"(r[0]), "=r"(r[1]), "=r"(r[2]), "=r"(r[3]) : "r"(addr));
}
__device__ __forceinline__ void mma_bf16(float c[4], const uint32_t a[4], const uint32_t b[2]) {
    asm volatile("mma.sync.aligned.m16n8k16.row.col.f32.bf16.bf16.f32 "
                 "{%0,%1,%2,%3}, {%4,%5,%6,%7}, {%8,%9}, {%0,%1,%2,%3};"
                 : "+f"(c[0]), "+f"(c[1]), "+f"(c[2]), "+f"(c[3])
                 : "r"(a[0]), "r"(a[1]), "r"(a[2]), "r"(a[3]), "r"(b[0]), "r"(b[1]));
}

__global__ void __launch_bounds__(256) out_gemm_tc(
    const float* __restrict__ outb, float* __restrict__ out)
{
    __shared__ __align__(16) __nv_bfloat16 sAH[128 * LDSW];
    __shared__ __align__(16) __nv_bfloat16 sAL[128 * LDSW];
    __shared__ __align__(16) __nv_bfloat16 sBH[128 * LDSW];
    __shared__ __align__(16) __nv_bfloat16 sBL[128 * LDSW];

    const int tid  = threadIdx.x;
    const int lane = tid & 31;
    const int w    = tid >> 5;
    const int wm   = w >> 2;
    const int wn   = w & 3;
    const int m0 = blockIdx.y * 128;
    const int n0 = blockIdx.x * 128;

    float acc[4][4][4];
#pragma unroll
    for (int mt = 0; mt < 4; mt++)
#pragma unroll
        for (int nt = 0; nt < 4; nt++)
#pragma unroll
            for (int r = 0; r < 4; r++) acc[mt][nt][r] = 0.f;

    const int a_row = lane & 15;
    const int a_k8  = (lane >> 4) * 8;
    const int b_nrw = (lane & 7) + ((lane >> 4) << 3);
    const int b_k8  = ((lane >> 3) & 1) * 8;

    const uint32_t uAH = s2u(sAH), uAL = s2u(sAL);
    const uint32_t uBH = s2u(sBH), uBL = s2u(sBL);

    for (int k0 = 0; k0 < 512; k0 += 32) {
        __syncthreads();
#pragma unroll
        for (int i = 0; i < 2; i++) {
            int v = tid + i * 256;
            int row = v >> 2;
            int kc  = (v & 3) * 8;
            size_t ga = (size_t)(m0 + row) * 512 + k0 + kc;
            size_t gb = (size_t)(n0 + row) * 512 + k0 + kc;
            int so = row * LDSW + kc;
            *(uint4*)(sAH + so) = *(const uint4*)(g_AH + ga);
            *(uint4*)(sAL + so) = *(const uint4*)(g_AL + ga);
            *(uint4*)(sBH + so) = *(const uint4*)(g_WH + gb);
            *(uint4*)(sBL + so) = *(const uint4*)(g_WL + gb);
        }
        __syncthreads();

#pragma unroll
        for (int ks = 0; ks < 32; ks += 16) {
            uint32_t aH[4][4], aL[4][4];
#pragma unroll
            for (int mt = 0; mt < 4; mt++) {
                int off = ((wm * 64 + mt * 16 + a_row) * LDSW + ks + a_k8) * 2;
                ldsm_x4(aH[mt], uAH + off);
                ldsm_x4(aL[mt], uAL + off);
            }
            uint32_t bH[4][2], bL[4][2];
#pragma unroll
            for (int p = 0; p < 2; p++) {
                int off = ((wn * 32 + p * 16 + b_nrw) * LDSW + ks + b_k8) * 2;
                uint32_t r[4];
                ldsm_x4(r, uBH + off);
                bH[2 * p][0] = r[0]; bH[2 * p][1] = r[1];
                bH[2 * p + 1][0] = r[2]; bH[2 * p + 1][1] = r[3];
                ldsm_x4(r, uBL + off);
                bL[2 * p][0] = r[0]; bL[2 * p][1] = r[1];
                bL[2 * p + 1][0] = r[2]; bL[2 * p + 1][1] = r[3];
            }
#pragma unroll
            for (int mt = 0; mt < 4; mt++)
#pragma unroll
                for (int nt = 0; nt < 4; nt++) {
                    mma_bf16(acc[mt][nt], aH[mt], bH[nt]);
                    mma_bf16(acc[mt][nt], aH[mt], bL[nt]);
                    mma_bf16(acc[mt][nt], aL[mt], bH[nt]);
                }
        }
    }

#pragma unroll
    for (int mt = 0; mt < 4; mt++) {
#pragma unroll
        for (int half = 0; half < 2; half++) {
            int m = m0 + wm * 64 + mt * 16 + (lane >> 2) + half * 8;
            int tt = m >> 5, b = m & 31;
            float* orow = out + ((size_t)b * SEQ + tt) * VV;
#pragma unroll
            for (int nt = 0; nt < 4; nt++) {
                int n = n0 + wn * 32 + nt * 8 + 2 * (lane & 3);
                float2 bias = *(const float2*)(outb + n);
                float2 v;
                v.x = acc[mt][nt][2 * half + 0] + bias.x;
                v.y = acc[mt][nt][2 * half + 1] + bias.y;
                *(float2*)(orow + n) = v;
            }
        }
    }
}

extern "C" void kernel_launch(void* const* d_in, const int* in_sizes, int n_in,
                              void* d_out, int out_size)
{
    const float* features = (const float*)d_in[0];
    const int*   captions = (const int*)d_in[1];
    const float* embed_W  = (const float*)d_in[2];
    const float* ihW = (const float*)d_in[3];
    const float* ihb = (const float*)d_in[4];
    const float* icW = (const float*)d_in[5];
    const float* icb = (const float*)d_in[6];
    const float* rW  = (const float*)d_in[7];
    const float* rb  = (const float*)d_in[8];
    const float* Wih = (const float*)d_in[9];
    const float* Whh = (const float*)d_in[10];
    const float* bih = (const float*)d_in[11];
    const float* bhh = (const float*)d_in[12];
    const float* outW = (const float*)d_in[13];
    const float* outb = (const float*)d_in[14];

    dim3 pgrid(8, 16);
    pre_wf<<<pgrid, 256>>>(Wih, rW);
    pre_bias<<<64, 256>>>(Wih, rb, bih, bhh);
    recurrence_kernel<<<NBLK, NTHR>>>(features, captions, embed_W,
                                      ihW, ihb, icW, icb, Whh);
    convert_kernel<<<2048, 256>>>(outW);
    dim3 grid(VV / 128, (SEQ * BB) / 128);
    out_gemm_tc<<<grid, 256>>>(outb, (float*)d_out);
}

// round 15
// speedup vs baseline: 1.4857x; 1.0200x over previous
#include <cuda_runtime.h>
#include <cuda_bf16.h>
#include <math.h>
#include <stdint.h>

#define BB 32
#define NREG 196
#define EE 512
#define HH 512
#define SEQ 64
#define VV 32000

#define NBLK 148
#define NTHR 512

// dynamic smem pool (floats)
#define OFF_W     0                      // 16*1536 = 24576
#define OFF_ACTA  24576                  // 4096
#define OFF_ACTB  28672                  // 4096
#define OFF_H     32768                  // 512
#define OFF_SC    33280                  // 256
#define OFF_ATTN  33536                  // 256
#define OFF_REDS  33792                  // 64
#define OFF_PART  33856                  // 2048 (16*128)
#define OFF_RED   35904                  // 2048 (16*4*32)
#define OFF_OUT   37952                  // 512
#define POOL_F    38464
#define POOL_BYTES (POOL_F * 4)

// ---------------- scratch (device globals; no allocations) ----------------
__device__ float g_fmean[BB * EE];
__device__ __align__(16) float g_hbuf[2][BB * HH];   // [b][k]
__device__ __align__(16) float g_hT[2][HH * BB];     // [k][b]
__device__ float g_cT[HH * BB];                      // [k][b]
__device__ __align__(16) float g_actCE[2 * EE * BB]; // [k][b]: ctx | emb*sqrtE
__device__ __align__(16) float g_Hall[SEQ * BB * HH];
__device__ __align__(16) float g_Wf[4 * HH * (EE + HH)]; // fused Wih@rW, rp-ordered rows
__device__ float g_bf[4 * HH];
__device__ unsigned g_bar_count;
__device__ unsigned g_bar_gen;

// bf16 split buffers for tensor-core GEMM
__device__ __align__(16) __nv_bfloat16 g_AH[SEQ * BB * HH];
__device__ __align__(16) __nv_bfloat16 g_AL[SEQ * BB * HH];
__device__ __align__(16) __nv_bfloat16 g_WH[(size_t)VV * EE];
__device__ __align__(16) __nv_bfloat16 g_WL[(size_t)VV * EE];

// ---------------- grid-wide barrier ----------------
__device__ __forceinline__ void gridbar() {
    __syncthreads();
    if (threadIdx.x == 0) {
        unsigned gen = *((volatile unsigned*)&g_bar_gen);
        __threadfence();
        if (atomicAdd(&g_bar_count, 1u) == (unsigned)(gridDim.x - 1)) {
            g_bar_count = 0;
            __threadfence();
            atomicAdd(&g_bar_gen, 1u);
        } else {
            while (*((volatile unsigned*)&g_bar_gen) == gen) { __nanosleep(32); }
        }
        __threadfence();
    }
    __syncthreads();
}

__device__ __forceinline__ float warpsum(float v) {
#pragma unroll
    for (int o = 16; o; o >>= 1) v += __shfl_xor_sync(0xffffffffu, v, o);
    return v;
}

__device__ __forceinline__ float warpdot512(const float* __restrict__ a,
                                            const float* __restrict__ b, int lane) {
    float s = 0.f;
#pragma unroll
    for (int c = 0; c < 4; c++) {
        float4 av = *(const float4*)(a + c * 128 + lane * 4);
        float4 bv = *(const float4*)(b + c * 128 + lane * 4);
        s += av.x * bv.x + av.y * bv.y + av.z * bv.z + av.w * bv.w;
    }
    return s;
}

// ---------------- precompute: Wf = Wih @ rW (rows permuted to rp order) ----------------
__global__ void __launch_bounds__(256) pre_wf(const float* __restrict__ Wih,
                                              const float* __restrict__ rW)
{
    __shared__ __align__(16) float As[16][128];
    __shared__ __align__(16) float Bs[16][128];
    const int bn = blockIdx.x;          // 0..7
    const int bm = blockIdx.y;          // 0..15
    const int tid = threadIdx.x;
    const int tx = tid & 15, ty = tid >> 4;

    float acc[8][8];
#pragma unroll
    for (int i = 0; i < 8; i++)
#pragma unroll
        for (int j = 0; j < 8; j++) acc[i][j] = 0.f;

    for (int k0 = 0; k0 < 512; k0 += 16) {
#pragma unroll
        for (int i = 0; i < 2; i++) {
            int f = tid + i * 256;
            int row = f >> 2;
            int cg  = (f & 3) * 4;
            int m = bm * 128 + row;
            int arow = (m & 3) * HH + (m >> 2);
            float4 va = *(const float4*)(Wih + (size_t)arow * EE + k0 + cg);
            As[cg + 0][row] = va.x; As[cg + 1][row] = va.y;
            As[cg + 2][row] = va.z; As[cg + 3][row] = va.w;
            int kk = f >> 5;
            int n4 = (f & 31) * 4;
            float4 vb = *(const float4*)(rW + (size_t)(k0 + kk) * (EE + HH) + bn * 128 + n4);
            *(float4*)&Bs[kk][n4] = vb;
        }
        __syncthreads();
#pragma unroll
        for (int kk = 0; kk < 16; kk++) {
            float a[8], b[8];
#pragma unroll
            for (int i = 0; i < 8; i += 4) {
                float4 v = *(const float4*)&As[kk][ty * 8 + i];
                a[i] = v.x; a[i + 1] = v.y; a[i + 2] = v.z; a[i + 3] = v.w;
            }
#pragma unroll
            for (int j = 0; j < 8; j += 4) {
                float4 v = *(const float4*)&Bs[kk][tx * 8 + j];
                b[j] = v.x; b[j + 1] = v.y; b[j + 2] = v.z; b[j + 3] = v.w;
            }
#pragma unroll
            for (int i = 0; i < 8; i++)
#pragma unroll
                for (int j = 0; j < 8; j++) acc[i][j] += a[i] * b[j];
        }
        __syncthreads();
    }
#pragma unroll
    for (int i = 0; i < 8; i++) {
        int m = bm * 128 + ty * 8 + i;
        float* crow = g_Wf + (size_t)m * (EE + HH) + bn * 128 + tx * 8;
#pragma unroll
        for (int j = 0; j < 8; j += 4) {
            float4 v;
            v.x = acc[i][j]; v.y = acc[i][j + 1]; v.z = acc[i][j + 2]; v.w = acc[i][j + 3];
            *(float4*)(crow + j) = v;
        }
    }
}

__global__ void __launch_bounds__(256) pre_bias(const float* __restrict__ Wih,
                                                const float* __restrict__ rb,
                                                const float* __restrict__ bih,
                                                const float* __restrict__ bhh)
{
    int lane = threadIdx.x & 31;
    int wid_g = (blockIdx.x * 256 + threadIdx.x) >> 5;
    int nw = (gridDim.x * 256) >> 5;
    for (int r = wid_g; r < 4 * HH; r += nw) {
        float s = warpsum(warpdot512(Wih + (size_t)r * EE, rb, lane));
        if (lane == 0) g_bf[r] = s + bih[r] + bhh[r];
    }
}

// ---------------- persistent recurrence kernel (weights resident in smem) ----------------
__global__ void __launch_bounds__(NTHR) recurrence_kernel(
    const float* __restrict__ features, const int* __restrict__ captions,
    const float* __restrict__ embed_W,
    const float* __restrict__ ihW, const float* __restrict__ ihb,
    const float* __restrict__ icW, const float* __restrict__ icb,
    const float* __restrict__ Whh)
{
    extern __shared__ __align__(16) float pool[];
    float* wSmem = pool + OFF_W;     // 16 rows x 1536, persistent
    float* actA  = pool + OFF_ACTA;
    float* actB  = pool + OFF_ACTB;
    float* sh_h  = pool + OFF_H;
    float* sSc   = pool + OFF_SC;
    float* sAttn = pool + OFF_ATTN;
    float* sRedS = pool + OFF_REDS;
    float* sPart = pool + OFF_PART;
    float* sRed  = pool + OFF_RED;
    float* sOut  = pool + OFF_OUT;

    const int tid  = threadIdx.x;
    const int lane = tid & 31;
    const int w    = tid >> 5;
    const int gtid = blockIdx.x * NTHR + tid;
    const int wid_g  = gtid >> 5;
    const int nwarps = (NBLK * NTHR) >> 5;
    const int gstride = NBLK * NTHR;

    // ---- init a: fmean
    for (int idx = gtid; idx < BB * EE; idx += gstride) {
        int b = idx >> 9, e = idx & 511;
        const float* fp = features + (size_t)b * NREG * EE + e;
        float s = 0.f;
        for (int n = 0; n < NREG; n++) s += fp[n * EE];
        g_fmean[idx] = s * (1.0f / NREG);
    }
    gridbar();

    // ---- init b: h0 / c0 (warp per output)
    for (int task = wid_g; task < 2 * BB * HH; task += nwarps) {
        int which = task & 1;
        int m = task >> 1;
        int b = m >> 9, eo = m & 511;
        const float* Wrow = (which ? icW : ihW) + (size_t)eo * EE;
        float s = warpsum(warpdot512(Wrow, g_fmean + b * EE, lane));
        if (lane == 0) {
            if (which) {
                g_cT[eo * BB + b] = s + icb[eo];
            } else {
                float hv = s + ihb[eo];
                g_hbuf[0][m] = hv;
                g_hT[0][eo * BB + b] = hv;
            }
        }
    }

    // ---- load this block's 16 gate rows (1536 wide) into persistent smem
    if (blockIdx.x < 128) {
        const int rp0 = blockIdx.x * 16;
        for (int i4 = tid; i4 < 6144; i4 += NTHR) {       // 6144 float4 = 16*1536
            int elem = i4 * 4;
            int rl  = elem / 1536;
            int off = elem - rl * 1536;
            float4 v;
            if (off < 1024) {
                v = *(const float4*)(g_Wf + (size_t)(rp0 + rl) * (EE + HH) + off);
            } else {
                int rp = rp0 + rl;
                int hi = rp >> 2, gate = rp & 3;
                v = *(const float4*)(Whh + (size_t)(gate * HH + hi) * HH + (off - 1024));
            }
            *(float4*)(wSmem + rl * 1536 + off) = v;
        }
    }
    gridbar();

    for (int t = 0; t < SEQ; t++) {
        const float* h_cur  = g_hbuf[t & 1];
        const float* hT_cur = g_hT[t & 1];
        float*       h_nxt  = g_hbuf[(t & 1) ^ 1];
        float*       hT_nxt = g_hT[(t & 1) ^ 1];

        // ==== P12: attention (scores redundant per (b,chunk) block) + emb fill
        if (blockIdx.x < 128) {
            const int b = blockIdx.x >> 2;
            const int chunk = blockIdx.x & 3;
            const float* fb = features + (size_t)b * NREG * EE;

            sh_h[tid] = h_cur[b * EE + tid];
            __syncthreads();

            for (int n = w; n < NREG; n += 16) {
                float s = warpsum(warpdot512(fb + (size_t)n * EE, sh_h, lane));
                if (lane == 0) sSc[n] = s;
            }
            __syncthreads();

            float v = (tid < NREG) ? sSc[tid] : -1e30f;
            float m = v;
#pragma unroll
            for (int o = 16; o; o >>= 1) m = fmaxf(m, __shfl_xor_sync(0xffffffffu, m, o));
            if (lane == 0) sRedS[w] = m;
            __syncthreads();
            float mx = sRedS[0];
#pragma unroll
            for (int i = 1; i < 16; i++) mx = fmaxf(mx, sRedS[i]);
            float ev = (tid < NREG) ? __expf(v - mx) : 0.f;
            float ps = warpsum(ev);
            __syncthreads();
            if (lane == 0) sRedS[w] = ps;
            __syncthreads();
            float tot = 0.f;
#pragma unroll
            for (int i = 0; i < 16; i++) tot += sRedS[i];
            if (tid < NREG) sAttn[tid] = ev / tot;
            __syncthreads();

            float4 cacc = make_float4(0.f, 0.f, 0.f, 0.f);
            const float* fc = fb + chunk * 128 + lane * 4;
#pragma unroll 4
            for (int n = w; n < NREG; n += 16) {
                float a = sAttn[n];
                float4 fv = *(const float4*)(fc + (size_t)n * EE);
                cacc.x += a * fv.x; cacc.y += a * fv.y;
                cacc.z += a * fv.z; cacc.w += a * fv.w;
            }
            *(float4*)(sPart + w * 128 + lane * 4) = cacc;
            __syncthreads();
            if (tid < 128) {
                float s = 0.f;
#pragma unroll
                for (int i = 0; i < 16; i++) s += sPart[i * 128 + tid];
                g_actCE[(chunk * 128 + tid) * BB + b] = s;
            }
        } else {
            for (int idx = (blockIdx.x - 128) * NTHR + tid; idx < BB * EE;
                 idx += 20 * NTHR) {
                int b = idx >> 9, k = idx & 511;
                int tok = captions[b * SEQ + t];
                g_actCE[(EE + k) * BB + b] =
                    embed_W[(size_t)tok * EE + k] * 22.62741699796952f; // sqrt(512)
            }
        }
        gridbar();

        // ==== P4': fused gates + cell. K = 1536; weights resident in smem;
        //           act double-buffered (1 sync per chunk)
        if (blockIdx.x < 128) {
            const int rg = w >> 2, qq = w & 3;
            float acc0 = 0.f, acc1 = 0.f, acc2 = 0.f, acc3 = 0.f;

            // preload chunk 0 into actA
            for (int i4 = tid; i4 < 1024; i4 += NTHR)
                ((float4*)actA)[i4] = ((const float4*)g_actCE)[i4];
            __syncthreads();

            for (int kc = 0; kc < 12; kc++) {
                float* cur = (kc & 1) ? actB : actA;
                float* nxt = (kc & 1) ? actA : actB;
                if (kc < 11) {
                    int kn = kc + 1;
                    const float* asrc = (kn < 8) ? (g_actCE + kn * 128 * BB)
                                                 : (hT_cur + (kn - 8) * 128 * BB);
                    for (int i4 = tid; i4 < 1024; i4 += NTHR)
                        ((float4*)nxt)[i4] = ((const float4*)asrc)[i4];
                }
                const float* w0p = wSmem + (rg * 4 + 0) * 1536 + kc * 128 + qq * 32;
                const float* w1p = wSmem + (rg * 4 + 1) * 1536 + kc * 128 + qq * 32;
                const float* w2p = wSmem + (rg * 4 + 2) * 1536 + kc * 128 + qq * 32;
                const float* w3p = wSmem + (rg * 4 + 3) * 1536 + kc * 128 + qq * 32;
#pragma unroll
                for (int k4 = 0; k4 < 32; k4 += 4) {
                    const float* ap = cur + (qq * 32 + k4) * BB + lane;
                    float a0 = ap[0 * BB], a1 = ap[1 * BB];
                    float a2 = ap[2 * BB], a3 = ap[3 * BB];
                    float4 w0 = *(const float4*)(w0p + k4);
                    float4 w1 = *(const float4*)(w1p + k4);
                    float4 w2 = *(const float4*)(w2p + k4);
                    float4 w3 = *(const float4*)(w3p + k4);
                    acc0 += w0.x * a0 + w0.y * a1 + w0.z * a2 + w0.w * a3;
                    acc1 += w1.x * a0 + w1.y * a1 + w1.z * a2 + w1.w * a3;
                    acc2 += w2.x * a0 + w2.y * a1 + w2.z * a2 + w2.w * a3;
                    acc3 += w3.x * a0 + w3.y * a1 + w3.z * a2 + w3.w * a3;
                }
                __syncthreads();
            }
            sRed[((rg * 4 + 0) * 4 + qq) * BB + lane] = acc0;
            sRed[((rg * 4 + 1) * 4 + qq) * BB + lane] = acc1;
            sRed[((rg * 4 + 2) * 4 + qq) * BB + lane] = acc2;
            sRed[((rg * 4 + 3) * 4 + qq) * BB + lane] = acc3;
            __syncthreads();
            {
                int rl = tid >> 5, b = tid & 31;
                float s = sRed[(rl * 4 + 0) * BB + b] + sRed[(rl * 4 + 1) * BB + b]
                        + sRed[(rl * 4 + 2) * BB + b] + sRed[(rl * 4 + 3) * BB + b];
                sOut[rl * BB + b] = s;
            }
            __syncthreads();
            if (tid < 128) {
                int hl = tid >> 5;
                int b  = tid & 31;
                int hi = blockIdx.x * 4 + hl;
                float iv = sOut[(hl * 4 + 0) * BB + b] + g_bf[hi];
                float fv = sOut[(hl * 4 + 1) * BB + b] + g_bf[HH + hi];
                float gv = sOut[(hl * 4 + 2) * BB + b] + g_bf[2 * HH + hi];
                float ov = sOut[(hl * 4 + 3) * BB + b] + g_bf[3 * HH + hi];
                float si = 1.f / (1.f + __expf(-iv));
                float sf = 1.f / (1.f + __expf(-fv));
                float so = 1.f / (1.f + __expf(-ov));
                float c2 = sf * g_cT[hi * BB + b] + si * tanhf(gv);
                float h2 = so * tanhf(c2);
                g_cT[hi * BB + b] = c2;
                hT_nxt[hi * BB + b] = h2;
                h_nxt[b * HH + hi] = h2;
                g_Hall[((size_t)t * BB + b) * HH + hi] = h2;
            }
        }
        gridbar();
    }
}

// ---------------- fp32 -> bf16 hi/lo split ----------------
__device__ __forceinline__ void split_store(float4 v, __nv_bfloat16* H,
                                            __nv_bfloat16* L, size_t off) {
    __nv_bfloat162 h0, h1, l0, l1;
    h0.x = __float2bfloat16(v.x); h0.y = __float2bfloat16(v.y);
    h1.x = __float2bfloat16(v.z); h1.y = __float2bfloat16(v.w);
    l0.x = __float2bfloat16(v.x - __bfloat162float(h0.x));
    l0.y = __float2bfloat16(v.y - __bfloat162float(h0.y));
    l1.x = __float2bfloat16(v.z - __bfloat162float(h1.x));
    l1.y = __float2bfloat16(v.w - __bfloat162float(h1.y));
    *(__nv_bfloat162*)(H + off) = h0; *(__nv_bfloat162*)(H + off + 2) = h1;
    *(__nv_bfloat162*)(L + off) = l0; *(__nv_bfloat162*)(L + off + 2) = l1;
}

__global__ void __launch_bounds__(256) convert_kernel(const float* __restrict__ outW)
{
    const size_t NW4 = ((size_t)VV * EE) / 4;
    const size_t NA4 = ((size_t)SEQ * BB * HH) / 4;
    size_t stride = (size_t)gridDim.x * blockDim.x;
    for (size_t i = (size_t)blockIdx.x * blockDim.x + threadIdx.x;
         i < NW4 + NA4; i += stride) {
        if (i < NW4) {
            float4 v = ((const float4*)outW)[i];
            split_store(v, g_WH, g_WL, i * 4);
        } else {
            size_t j = i - NW4;
            float4 v = ((const float4*)g_Hall)[j];
            split_store(v, g_AH, g_AL, j * 4);
        }
    }
}

// ---------------- tensor-core output GEMM ----------------
#define LDSW 40

__device__ __forceinline__ uint32_t s2u(const void* p) {
    return (uint32_t)__cvta_generic_to_shared(p);
}
__device__ __forceinline__ void ldsm_x4(uint32_t r[4], uint32_t addr) {
    asm volatile("ldmatrix.sync.aligned.m8n8.x4.shared.b16 {%0,%1,%2,%3}, [%4];"
                 : "=r"(r[0]), "=r"(r[1]), "=r"(r[2]), "=r"(r[3]) : "r"(addr));
}
__device__ __forceinline__ void mma_bf16(float c[4], const uint32_t a[4], const uint32_t b[2]) {
    asm volatile("mma.sync.aligned.m16n8k16.row.col.f32.bf16.bf16.f32 "
                 "{%0,%1,%2,%3}, {%4,%5,%6,%7}, {%8,%9}, {%0,%1,%2,%3};"
                 : "+f"(c[0]), "+f"(c[1]), "+f"(c[2]), "+f"(c[3])
                 : "r"(a[0]), "r"(a[1]), "r"(a[2]), "r"(a[3]), "r"(b[0]), "r"(b[1]));
}

__global__ void __launch_bounds__(256) out_gemm_tc(
    const float* __restrict__ outb, float* __restrict__ out)
{
    __shared__ __align__(16) __nv_bfloat16 sAH[128 * LDSW];
    __shared__ __align__(16) __nv_bfloat16 sAL[128 * LDSW];
    __shared__ __align__(16) __nv_bfloat16 sBH[128 * LDSW];
    __shared__ __align__(16) __nv_bfloat16 sBL[128 * LDSW];

    const int tid  = threadIdx.x;
    const int lane = tid & 31;
    const int w    = tid >> 5;
    const int wm   = w >> 2;
    const int wn   = w & 3;
    const int m0 = blockIdx.y * 128;
    const int n0 = blockIdx.x * 128;

    float acc[4][4][4];
#pragma unroll
    for (int mt = 0; mt < 4; mt++)
#pragma unroll
        for (int nt = 0; nt < 4; nt++)
#pragma unroll
            for (int r = 0; r < 4; r++) acc[mt][nt][r] = 0.f;

    const int a_row = lane & 15;
    const int a_k8  = (lane >> 4) * 8;
    const int b_nrw = (lane & 7) + ((lane >> 4) << 3);
    const int b_k8  = ((lane >> 3) & 1) * 8;

    const uint32_t uAH = s2u(sAH), uAL = s2u(sAL);
    const uint32_t uBH = s2u(sBH), uBL = s2u(sBL);

    for (int k0 = 0; k0 < 512; k0 += 32) {
        __syncthreads();
#pragma unroll
        for (int i = 0; i < 2; i++) {
            int v = tid + i * 256;
            int row = v >> 2;
            int kc  = (v & 3) * 8;
            size_t ga = (size_t)(m0 + row) * 512 + k0 + kc;
            size_t gb = (size_t)(n0 + row) * 512 + k0 + kc;
            int so = row * LDSW + kc;
            *(uint4*)(sAH + so) = *(const uint4*)(g_AH + ga);
            *(uint4*)(sAL + so) = *(const uint4*)(g_AL + ga);
            *(uint4*)(sBH + so) = *(const uint4*)(g_WH + gb);
            *(uint4*)(sBL + so) = *(const uint4*)(g_WL + gb);
        }
        __syncthreads();

#pragma unroll
        for (int ks = 0; ks < 32; ks += 16) {
            uint32_t aH[4][4], aL[4][4];
#pragma unroll
            for (int mt = 0; mt < 4; mt++) {
                int off = ((wm * 64 + mt * 16 + a_row) * LDSW + ks + a_k8) * 2;
                ldsm_x4(aH[mt], uAH + off);
                ldsm_x4(aL[mt], uAL + off);
            }
            uint32_t bH[4][2], bL[4][2];
#pragma unroll
            for (int p = 0; p < 2; p++) {
                int off = ((wn * 32 + p * 16 + b_nrw) * LDSW + ks + b_k8) * 2;
                uint32_t r[4];
                ldsm_x4(r, uBH + off);
                bH[2 * p][0] = r[0]; bH[2 * p][1] = r[1];
                bH[2 * p + 1][0] = r[2]; bH[2 * p + 1][1] = r[3];
                ldsm_x4(r, uBL + off);
                bL[2 * p][0] = r[0]; bL[2 * p][1] = r[1];
                bL[2 * p + 1][0] = r[2]; bL[2 * p + 1][1] = r[3];
            }
#pragma unroll
            for (int mt = 0; mt < 4; mt++)
#pragma unroll
                for (int nt = 0; nt < 4; nt++) {
                    mma_bf16(acc[mt][nt], aH[mt], bH[nt]);
                    mma_bf16(acc[mt][nt], aH[mt], bL[nt]);
                    mma_bf16(acc[mt][nt], aL[mt], bH[nt]);
                }
        }
    }

#pragma unroll
    for (int mt = 0; mt < 4; mt++) {
#pragma unroll
        for (int half = 0; half < 2; half++) {
            int m = m0 + wm * 64 + mt * 16 + (lane >> 2) + half * 8;
            int tt = m >> 5, b = m & 31;
            float* orow = out + ((size_t)b * SEQ + tt) * VV;
#pragma unroll
            for (int nt = 0; nt < 4; nt++) {
                int n = n0 + wn * 32 + nt * 8 + 2 * (lane & 3);
                float2 bias = *(const float2*)(outb + n);
                float2 v;
                v.x = acc[mt][nt][2 * half + 0] + bias.x;
                v.y = acc[mt][nt][2 * half + 1] + bias.y;
                *(float2*)(orow + n) = v;
            }
        }
    }
}

extern "C" void kernel_launch(void* const* d_in, const int* in_sizes, int n_in,
                              void* d_out, int out_size)
{
    const float* features = (const float*)d_in[0];
    const int*   captions = (const int*)d_in[1];
    const float* embed_W  = (const float*)d_in[2];
    const float* ihW = (const float*)d_in[3];
    const float* ihb = (const float*)d_in[4];
    const float* icW = (const float*)d_in[5];
    const float* icb = (const float*)d_in[6];
    const float* rW  = (const float*)d_in[7];
    const float* rb  = (const float*)d_in[8];
    const float* Wih = (const float*)d_in[9];
    const float* Whh = (const float*)d_in[10];
    const float* bih = (const float*)d_in[11];
    const float* bhh = (const float*)d_in[12];
    const float* outW = (const float*)d_in[13];
    const float* outb = (const float*)d_in[14];

    cudaFuncSetAttribute(recurrence_kernel,
                         cudaFuncAttributeMaxDynamicSharedMemorySize, POOL_BYTES);

    dim3 pgrid(8, 16);
    pre_wf<<<pgrid, 256>>>(Wih, rW);
    pre_bias<<<64, 256>>>(Wih, rb, bih, bhh);
    recurrence_kernel<<<NBLK, NTHR, POOL_BYTES>>>(features, captions, embed_W,
                                                  ihW, ihb, icW, icb, Whh);
    convert_kernel<<<2048, 256>>>(outW);
    dim3 grid(VV / 128, (SEQ * BB) / 128);
    out_gemm_tc<<<grid, 256>>>(outb, (float*)d_out);
}

// round 16
// speedup vs baseline: 1.5338x; 1.0323x over previous
#include <cuda_runtime.h>
#include <cuda_bf16.h>
#include <math.h>
#include <stdint.h>

#define BB 32
#define NREG 196
#define EE 512
#define HH 512
#define SEQ 64
#define VV 32000

#define NBLK 148
#define NTHR 512

// dynamic smem pool (floats)
#define OFF_W     0                      // 16*1536 = 24576
#define OFF_ACTA  24576                  // 4096
#define OFF_ACTB  28672                  // 4096
#define OFF_H     32768                  // 512
#define OFF_SC    33280                  // 256
#define OFF_ATTN  33536                  // 256
#define OFF_REDS  33792                  // 64
#define OFF_PART  33856                  // 2048 (16*128)
#define OFF_RED   35904                  // 2048 (16*4*32)
#define OFF_OUT   37952                  // 512
#define POOL_F    38464
#define POOL_BYTES (POOL_F * 4)

// ---------------- scratch (device globals; no allocations) ----------------
__device__ float g_fmean[BB * EE];
__device__ __align__(16) float g_hbuf[2][BB * HH];   // [b][k]
__device__ __align__(16) float g_hT[2][HH * BB];     // [k][b]
__device__ float g_cT[HH * BB];                      // [k][b]
__device__ __align__(16) float g_ctxT[EE * BB];      // [k][b] context
__device__ __align__(16) float g_embT[SEQ * EE * BB];// [t][k][b] emb*sqrtE, 4MB
__device__ __align__(16) float g_Hall[SEQ * BB * HH];
__device__ __align__(16) float g_Wf[4 * HH * (EE + HH)]; // fused Wih@rW, rp-ordered rows
__device__ float g_bf[4 * HH];
__device__ unsigned g_bar_count;
__device__ unsigned g_bar_gen;

// bf16 split buffers for tensor-core GEMM
__device__ __align__(16) __nv_bfloat16 g_AH[SEQ * BB * HH];
__device__ __align__(16) __nv_bfloat16 g_AL[SEQ * BB * HH];
__device__ __align__(16) __nv_bfloat16 g_WH[(size_t)VV * EE];
__device__ __align__(16) __nv_bfloat16 g_WL[(size_t)VV * EE];

// ---------------- grid-wide barrier ----------------
__device__ __forceinline__ void gridbar() {
    __syncthreads();
    if (threadIdx.x == 0) {
        unsigned gen = *((volatile unsigned*)&g_bar_gen);
        __threadfence();
        if (atomicAdd(&g_bar_count, 1u) == (unsigned)(gridDim.x - 1)) {
            g_bar_count = 0;
            __threadfence();
            atomicAdd(&g_bar_gen, 1u);
        } else {
            while (*((volatile unsigned*)&g_bar_gen) == gen) { __nanosleep(32); }
        }
        __threadfence();
    }
    __syncthreads();
}

__device__ __forceinline__ float warpsum(float v) {
#pragma unroll
    for (int o = 16; o; o >>= 1) v += __shfl_xor_sync(0xffffffffu, v, o);
    return v;
}

// two independent reductions, interleaved (overlapping shfl chains)
__device__ __forceinline__ void warpsum2(float& a, float& b) {
#pragma unroll
    for (int o = 16; o; o >>= 1) {
        a += __shfl_xor_sync(0xffffffffu, a, o);
        b += __shfl_xor_sync(0xffffffffu, b, o);
    }
}

__device__ __forceinline__ float warpdot512(const float* __restrict__ a,
                                            const float* __restrict__ b, int lane) {
    float s = 0.f;
#pragma unroll
    for (int c = 0; c < 4; c++) {
        float4 av = *(const float4*)(a + c * 128 + lane * 4);
        float4 bv = *(const float4*)(b + c * 128 + lane * 4);
        s += av.x * bv.x + av.y * bv.y + av.z * bv.z + av.w * bv.w;
    }
    return s;
}

// ---------------- precompute: embeddings for all steps ----------------
// g_embT[t][k][b] = embed_W[captions[b][t]][k] * sqrt(512)
__global__ void __launch_bounds__(256) pre_emb(const int* __restrict__ captions,
                                               const float* __restrict__ embed_W)
{
    int idx = blockIdx.x * 256 + threadIdx.x;     // < SEQ*EE*BB
    int b = idx & 31;
    int k = (idx >> 5) & 511;
    int t = idx >> 14;
    int tok = captions[b * SEQ + t];
    g_embT[idx] = embed_W[(size_t)tok * EE + k] * 22.62741699796952f;
}

// ---------------- precompute: Wf = Wih @ rW (rows permuted to rp order) ----------------
__global__ void __launch_bounds__(256) pre_wf(const float* __restrict__ Wih,
                                              const float* __restrict__ rW)
{
    __shared__ __align__(16) float As[16][128];
    __shared__ __align__(16) float Bs[16][128];
    const int bn = blockIdx.x;          // 0..7
    const int bm = blockIdx.y;          // 0..15
    const int tid = threadIdx.x;
    const int tx = tid & 15, ty = tid >> 4;

    float acc[8][8];
#pragma unroll
    for (int i = 0; i < 8; i++)
#pragma unroll
        for (int j = 0; j < 8; j++) acc[i][j] = 0.f;

    for (int k0 = 0; k0 < 512; k0 += 16) {
#pragma unroll
        for (int i = 0; i < 2; i++) {
            int f = tid + i * 256;
            int row = f >> 2;
            int cg  = (f & 3) * 4;
            int m = bm * 128 + row;
            int arow = (m & 3) * HH + (m >> 2);
            float4 va = *(const float4*)(Wih + (size_t)arow * EE + k0 + cg);
            As[cg + 0][row] = va.x; As[cg + 1][row] = va.y;
            As[cg + 2][row] = va.z; As[cg + 3][row] = va.w;
            int kk = f >> 5;
            int n4 = (f & 31) * 4;
            float4 vb = *(const float4*)(rW + (size_t)(k0 + kk) * (EE + HH) + bn * 128 + n4);
            *(float4*)&Bs[kk][n4] = vb;
        }
        __syncthreads();
#pragma unroll
        for (int kk = 0; kk < 16; kk++) {
            float a[8], b[8];
#pragma unroll
            for (int i = 0; i < 8; i += 4) {
                float4 v = *(const float4*)&As[kk][ty * 8 + i];
                a[i] = v.x; a[i + 1] = v.y; a[i + 2] = v.z; a[i + 3] = v.w;
            }
#pragma unroll
            for (int j = 0; j < 8; j += 4) {
                float4 v = *(const float4*)&Bs[kk][tx * 8 + j];
                b[j] = v.x; b[j + 1] = v.y; b[j + 2] = v.z; b[j + 3] = v.w;
            }
#pragma unroll
            for (int i = 0; i < 8; i++)
#pragma unroll
                for (int j = 0; j < 8; j++) acc[i][j] += a[i] * b[j];
        }
        __syncthreads();
    }
#pragma unroll
    for (int i = 0; i < 8; i++) {
        int m = bm * 128 + ty * 8 + i;
        float* crow = g_Wf + (size_t)m * (EE + HH) + bn * 128 + tx * 8;
#pragma unroll
        for (int j = 0; j < 8; j += 4) {
            float4 v;
            v.x = acc[i][j]; v.y = acc[i][j + 1]; v.z = acc[i][j + 2]; v.w = acc[i][j + 3];
            *(float4*)(crow + j) = v;
        }
    }
}

__global__ void __launch_bounds__(256) pre_bias(const float* __restrict__ Wih,
                                                const float* __restrict__ rb,
                                                const float* __restrict__ bih,
                                                const float* __restrict__ bhh)
{
    int lane = threadIdx.x & 31;
    int wid_g = (blockIdx.x * 256 + threadIdx.x) >> 5;
    int nw = (gridDim.x * 256) >> 5;
    for (int r = wid_g; r < 4 * HH; r += nw) {
        float s = warpsum(warpdot512(Wih + (size_t)r * EE, rb, lane));
        if (lane == 0) g_bf[r] = s + bih[r] + bhh[r];
    }
}

// ---------------- persistent recurrence kernel ----------------
__global__ void __launch_bounds__(NTHR) recurrence_kernel(
    const float* __restrict__ features,
    const float* __restrict__ ihW, const float* __restrict__ ihb,
    const float* __restrict__ icW, const float* __restrict__ icb,
    const float* __restrict__ Whh)
{
    extern __shared__ __align__(16) float pool[];
    float* wSmem = pool + OFF_W;
    float* actA  = pool + OFF_ACTA;
    float* actB  = pool + OFF_ACTB;
    float* sh_h  = pool + OFF_H;
    float* sSc   = pool + OFF_SC;
    float* sAttn = pool + OFF_ATTN;
    float* sRedS = pool + OFF_REDS;
    float* sPart = pool + OFF_PART;
    float* sRed  = pool + OFF_RED;
    float* sOut  = pool + OFF_OUT;

    const int tid  = threadIdx.x;
    const int lane = tid & 31;
    const int w    = tid >> 5;
    const int gtid = blockIdx.x * NTHR + tid;
    const int wid_g  = gtid >> 5;
    const int nwarps = (NBLK * NTHR) >> 5;
    const int gstride = NBLK * NTHR;

    // ---- init a: fmean
    for (int idx = gtid; idx < BB * EE; idx += gstride) {
        int b = idx >> 9, e = idx & 511;
        const float* fp = features + (size_t)b * NREG * EE + e;
        float s = 0.f;
        for (int n = 0; n < NREG; n++) s += fp[n * EE];
        g_fmean[idx] = s * (1.0f / NREG);
    }
    gridbar();

    // ---- init b: h0 / c0 (warp per output)
    for (int task = wid_g; task < 2 * BB * HH; task += nwarps) {
        int which = task & 1;
        int m = task >> 1;
        int b = m >> 9, eo = m & 511;
        const float* Wrow = (which ? icW : ihW) + (size_t)eo * EE;
        float s = warpsum(warpdot512(Wrow, g_fmean + b * EE, lane));
        if (lane == 0) {
            if (which) {
                g_cT[eo * BB + b] = s + icb[eo];
            } else {
                float hv = s + ihb[eo];
                g_hbuf[0][m] = hv;
                g_hT[0][eo * BB + b] = hv;
            }
        }
    }

    // ---- load this block's 16 gate rows (1536 wide) into persistent smem
    if (blockIdx.x < 128) {
        const int rp0 = blockIdx.x * 16;
        for (int i4 = tid; i4 < 6144; i4 += NTHR) {
            int elem = i4 * 4;
            int rl  = elem / 1536;
            int off = elem - rl * 1536;
            float4 v;
            if (off < 1024) {
                v = *(const float4*)(g_Wf + (size_t)(rp0 + rl) * (EE + HH) + off);
            } else {
                int rp = rp0 + rl;
                int hi = rp >> 2, gate = rp & 3;
                v = *(const float4*)(Whh + (size_t)(gate * HH + hi) * HH + (off - 1024));
            }
            *(float4*)(wSmem + rl * 1536 + off) = v;
        }
    }
    gridbar();

    for (int t = 0; t < SEQ; t++) {
        const float* h_cur  = g_hbuf[t & 1];
        const float* hT_cur = g_hT[t & 1];
        float*       h_nxt  = g_hbuf[(t & 1) ^ 1];
        float*       hT_nxt = g_hT[(t & 1) ^ 1];

        // ==== P12: attention (scores redundant per (b,chunk) block)
        if (blockIdx.x < 128) {
            const int b = blockIdx.x >> 2;
            const int chunk = blockIdx.x & 3;
            const float* fb = features + (size_t)b * NREG * EE;

            sh_h[tid] = h_cur[b * EE + tid];
            __syncthreads();

            // scores: 2-way n interleave per warp
            for (int n0i = w; n0i < NREG; n0i += 32) {
                int n1i = n0i + 16;
                bool has1 = (n1i < NREG);
                const float* f0 = fb + (size_t)n0i * EE;
                const float* f1 = fb + (size_t)(has1 ? n1i : n0i) * EE;
                float s0 = 0.f, s1 = 0.f;
#pragma unroll
                for (int c = 0; c < 4; c++) {
                    float4 hv = *(const float4*)(sh_h + c * 128 + lane * 4);
                    float4 a0 = *(const float4*)(f0 + c * 128 + lane * 4);
                    float4 a1 = *(const float4*)(f1 + c * 128 + lane * 4);
                    s0 += a0.x * hv.x + a0.y * hv.y + a0.z * hv.z + a0.w * hv.w;
                    s1 += a1.x * hv.x + a1.y * hv.y + a1.z * hv.z + a1.w * hv.w;
                }
                warpsum2(s0, s1);
                if (lane == 0) {
                    sSc[n0i] = s0;
                    if (has1) sSc[n1i] = s1;
                }
            }
            __syncthreads();

            float v = (tid < NREG) ? sSc[tid] : -1e30f;
            float m = v;
#pragma unroll
            for (int o = 16; o; o >>= 1) m = fmaxf(m, __shfl_xor_sync(0xffffffffu, m, o));
            if (lane == 0) sRedS[w] = m;
            __syncthreads();
            float mx = sRedS[0];
#pragma unroll
            for (int i = 1; i < 16; i++) mx = fmaxf(mx, sRedS[i]);
            float ev = (tid < NREG) ? __expf(v - mx) : 0.f;
            float ps = warpsum(ev);
            __syncthreads();
            if (lane == 0) sRedS[w] = ps;
            __syncthreads();
            float tot = 0.f;
#pragma unroll
            for (int i = 0; i < 16; i++) tot += sRedS[i];
            if (tid < NREG) sAttn[tid] = ev / tot;
            __syncthreads();

            float4 cacc = make_float4(0.f, 0.f, 0.f, 0.f);
            const float* fc = fb + chunk * 128 + lane * 4;
#pragma unroll 4
            for (int n = w; n < NREG; n += 16) {
                float a = sAttn[n];
                float4 fv = *(const float4*)(fc + (size_t)n * EE);
                cacc.x += a * fv.x; cacc.y += a * fv.y;
                cacc.z += a * fv.z; cacc.w += a * fv.w;
            }
            *(float4*)(sPart + w * 128 + lane * 4) = cacc;
            __syncthreads();
            if (tid < 128) {
                float s = 0.f;
#pragma unroll
                for (int i = 0; i < 16; i++) s += sPart[i * 128 + tid];
                g_ctxT[(chunk * 128 + tid) * BB + b] = s;
            }
        }
        gridbar();

        // ==== P4': fused gates + cell. K = 1536; weights resident in smem;
        //           act double-buffered; emb precomputed
        if (blockIdx.x < 128) {
            const int rg = w >> 2, qq = w & 3;
            float acc0 = 0.f, acc1 = 0.f, acc2 = 0.f, acc3 = 0.f;
            const float* embT_t = g_embT + (size_t)t * EE * BB;

            for (int i4 = tid; i4 < 1024; i4 += NTHR)
                ((float4*)actA)[i4] = ((const float4*)g_ctxT)[i4];
            __syncthreads();

            for (int kc = 0; kc < 12; kc++) {
                float* cur = (kc & 1) ? actB : actA;
                float* nxt = (kc & 1) ? actA : actB;
                if (kc < 11) {
                    int kn = kc + 1;
                    const float* asrc = (kn < 4) ? (g_ctxT + kn * 128 * BB)
                                      : (kn < 8) ? (embT_t + (kn - 4) * 128 * BB)
                                                 : (hT_cur + (kn - 8) * 128 * BB);
                    for (int i4 = tid; i4 < 1024; i4 += NTHR)
                        ((float4*)nxt)[i4] = ((const float4*)asrc)[i4];
                }
                const float* w0p = wSmem + (rg * 4 + 0) * 1536 + kc * 128 + qq * 32;
                const float* w1p = wSmem + (rg * 4 + 1) * 1536 + kc * 128 + qq * 32;
                const float* w2p = wSmem + (rg * 4 + 2) * 1536 + kc * 128 + qq * 32;
                const float* w3p = wSmem + (rg * 4 + 3) * 1536 + kc * 128 + qq * 32;
#pragma unroll
                for (int k4 = 0; k4 < 32; k4 += 4) {
                    const float* ap = cur + (qq * 32 + k4) * BB + lane;
                    float a0 = ap[0 * BB], a1 = ap[1 * BB];
                    float a2 = ap[2 * BB], a3 = ap[3 * BB];
                    float4 w0 = *(const float4*)(w0p + k4);
                    float4 w1 = *(const float4*)(w1p + k4);
                    float4 w2 = *(const float4*)(w2p + k4);
                    float4 w3 = *(const float4*)(w3p + k4);
                    acc0 += w0.x * a0 + w0.y * a1 + w0.z * a2 + w0.w * a3;
                    acc1 += w1.x * a0 + w1.y * a1 + w1.z * a2 + w1.w * a3;
                    acc2 += w2.x * a0 + w2.y * a1 + w2.z * a2 + w2.w * a3;
                    acc3 += w3.x * a0 + w3.y * a1 + w3.z * a2 + w3.w * a3;
                }
                __syncthreads();
            }
            sRed[((rg * 4 + 0) * 4 + qq) * BB + lane] = acc0;
            sRed[((rg * 4 + 1) * 4 + qq) * BB + lane] = acc1;
            sRed[((rg * 4 + 2) * 4 + qq) * BB + lane] = acc2;
            sRed[((rg * 4 + 3) * 4 + qq) * BB + lane] = acc3;
            __syncthreads();
            {
                int rl = tid >> 5, b = tid & 31;
                float s = sRed[(rl * 4 + 0) * BB + b] + sRed[(rl * 4 + 1) * BB + b]
                        + sRed[(rl * 4 + 2) * BB + b] + sRed[(rl * 4 + 3) * BB + b];
                sOut[rl * BB + b] = s;
            }
            __syncthreads();
            if (tid < 128) {
                int hl = tid >> 5;
                int b  = tid & 31;
                int hi = blockIdx.x * 4 + hl;
                float iv = sOut[(hl * 4 + 0) * BB + b] + g_bf[hi];
                float fv = sOut[(hl * 4 + 1) * BB + b] + g_bf[HH + hi];
                float gv = sOut[(hl * 4 + 2) * BB + b] + g_bf[2 * HH + hi];
                float ov = sOut[(hl * 4 + 3) * BB + b] + g_bf[3 * HH + hi];
                float si = 1.f / (1.f + __expf(-iv));
                float sf = 1.f / (1.f + __expf(-fv));
                float so = 1.f / (1.f + __expf(-ov));
                float c2 = sf * g_cT[hi * BB + b] + si * tanhf(gv);
                float h2 = so * tanhf(c2);
                g_cT[hi * BB + b] = c2;
                hT_nxt[hi * BB + b] = h2;
                h_nxt[b * HH + hi] = h2;
                g_Hall[((size_t)t * BB + b) * HH + hi] = h2;
            }
        }
        gridbar();
    }
}

// ---------------- fp32 -> bf16 hi/lo split ----------------
__device__ __forceinline__ void split_store(float4 v, __nv_bfloat16* H,
                                            __nv_bfloat16* L, size_t off) {
    __nv_bfloat162 h0, h1, l0, l1;
    h0.x = __float2bfloat16(v.x); h0.y = __float2bfloat16(v.y);
    h1.x = __float2bfloat16(v.z); h1.y = __float2bfloat16(v.w);
    l0.x = __float2bfloat16(v.x - __bfloat162float(h0.x));
    l0.y = __float2bfloat16(v.y - __bfloat162float(h0.y));
    l1.x = __float2bfloat16(v.z - __bfloat162float(h1.x));
    l1.y = __float2bfloat16(v.w - __bfloat162float(h1.y));
    *(__nv_bfloat162*)(H + off) = h0; *(__nv_bfloat162*)(H + off + 2) = h1;
    *(__nv_bfloat162*)(L + off) = l0; *(__nv_bfloat162*)(L + off + 2) = l1;
}

__global__ void __launch_bounds__(256) convert_kernel(const float* __restrict__ outW)
{
    const size_t NW4 = ((size_t)VV * EE) / 4;
    const size_t NA4 = ((size_t)SEQ * BB * HH) / 4;
    size_t stride = (size_t)gridDim.x * blockDim.x;
    for (size_t i = (size_t)blockIdx.x * blockDim.x + threadIdx.x;
         i < NW4 + NA4; i += stride) {
        if (i < NW4) {
            float4 v = ((const float4*)outW)[i];
            split_store(v, g_WH, g_WL, i * 4);
        } else {
            size_t j = i - NW4;
            float4 v = ((const float4*)g_Hall)[j];
            split_store(v, g_AH, g_AL, j * 4);
        }
    }
}

// ---------------- tensor-core output GEMM ----------------
#define LDSW 40

__device__ __forceinline__ uint32_t s2u(const void* p) {
    return (uint32_t)__cvta_generic_to_shared(p);
}
__device__ __forceinline__ void ldsm_x4(uint32_t r[4], uint32_t addr) {
    asm volatile("ldmatrix.sync.aligned.m8n8.x4.shared.b16 {%0,%1,%2,%3}, [%4];"
                 : "=r"(r[0]), "=r"(r[1]), "=r"(r[2]), "=r"(r[3]) : "r"(addr));
}
__device__ __forceinline__ void mma_bf16(float c[4], const uint32_t a[4], const uint32_t b[2]) {
    asm volatile("mma.sync.aligned.m16n8k16.row.col.f32.bf16.bf16.f32 "
                 "{%0,%1,%2,%3}, {%4,%5,%6,%7}, {%8,%9}, {%0,%1,%2,%3};"
                 : "+f"(c[0]), "+f"(c[1]), "+f"(c[2]), "+f"(c[3])
                 : "r"(a[0]), "r"(a[1]), "r"(a[2]), "r"(a[3]), "r"(b[0]), "r"(b[1]));
}

__global__ void __launch_bounds__(256) out_gemm_tc(
    const float* __restrict__ outb, float* __restrict__ out)
{
    __shared__ __align__(16) __nv_bfloat16 sAH[128 * LDSW];
    __shared__ __align__(16) __nv_bfloat16 sAL[128 * LDSW];
    __shared__ __align__(16) __nv_bfloat16 sBH[128 * LDSW];
    __shared__ __align__(16) __nv_bfloat16 sBL[128 * LDSW];

    const int tid  = threadIdx.x;
    const int lane = tid & 31;
    const int w    = tid >> 5;
    const int wm   = w >> 2;
    const int wn   = w & 3;
    const int m0 = blockIdx.y * 128;
    const int n0 = blockIdx.x * 128;

    float acc[4][4][4];
#pragma unroll
    for (int mt = 0; mt < 4; mt++)
#pragma unroll
        for (int nt = 0; nt < 4; nt++)
#pragma unroll
            for (int r = 0; r < 4; r++) acc[mt][nt][r] = 0.f;

    const int a_row = lane & 15;
    const int a_k8  = (lane >> 4) * 8;
    const int b_nrw = (lane & 7) + ((lane >> 4) << 3);
    const int b_k8  = ((lane >> 3) & 1) * 8;

    const uint32_t uAH = s2u(sAH), uAL = s2u(sAL);
    const uint32_t uBH = s2u(sBH), uBL = s2u(sBL);

    for (int k0 = 0; k0 < 512; k0 += 32) {
        __syncthreads();
#pragma unroll
        for (int i = 0; i < 2; i++) {
            int v = tid + i * 256;
            int row = v >> 2;
            int kc  = (v & 3) * 8;
            size_t ga = (size_t)(m0 + row) * 512 + k0 + kc;
            size_t gb = (size_t)(n0 + row) * 512 + k0 + kc;
            int so = row * LDSW + kc;
            *(uint4*)(sAH + so) = *(const uint4*)(g_AH + ga);
            *(uint4*)(sAL + so) = *(const uint4*)(g_AL + ga);
            *(uint4*)(sBH + so) = *(const uint4*)(g_WH + gb);
            *(uint4*)(sBL + so) = *(const uint4*)(g_WL + gb);
        }
        __syncthreads();

#pragma unroll
        for (int ks = 0; ks < 32; ks += 16) {
            uint32_t aH[4][4], aL[4][4];
#pragma unroll
            for (int mt = 0; mt < 4; mt++) {
                int off = ((wm * 64 + mt * 16 + a_row) * LDSW + ks + a_k8) * 2;
                ldsm_x4(aH[mt], uAH + off);
                ldsm_x4(aL[mt], uAL + off);
            }
            uint32_t bH[4][2], bL[4][2];
#pragma unroll
            for (int p = 0; p < 2; p++) {
                int off = ((wn * 32 + p * 16 + b_nrw) * LDSW + ks + b_k8) * 2;
                uint32_t r[4];
                ldsm_x4(r, uBH + off);
                bH[2 * p][0] = r[0]; bH[2 * p][1] = r[1];
                bH[2 * p + 1][0] = r[2]; bH[2 * p + 1][1] = r[3];
                ldsm_x4(r, uBL + off);
                bL[2 * p][0] = r[0]; bL[2 * p][1] = r[1];
                bL[2 * p + 1][0] = r[2]; bL[2 * p + 1][1] = r[3];
            }
#pragma unroll
            for (int mt = 0; mt < 4; mt++)
#pragma unroll
                for (int nt = 0; nt < 4; nt++) {
                    mma_bf16(acc[mt][nt], aH[mt], bH[nt]);
                    mma_bf16(acc[mt][nt], aH[mt], bL[nt]);
                    mma_bf16(acc[mt][nt], aL[mt], bH[nt]);
                }
        }
    }

#pragma unroll
    for (int mt = 0; mt < 4; mt++) {
#pragma unroll
        for (int half = 0; half < 2; half++) {
            int m = m0 + wm * 64 + mt * 16 + (lane >> 2) + half * 8;
            int tt = m >> 5, b = m & 31;
            float* orow = out + ((size_t)b * SEQ + tt) * VV;
#pragma unroll
            for (int nt = 0; nt < 4; nt++) {
                int n = n0 + wn * 32 + nt * 8 + 2 * (lane & 3);
                float2 bias = *(const float2*)(outb + n);
                float2 v;
                v.x = acc[mt][nt][2 * half + 0] + bias.x;
                v.y = acc[mt][nt][2 * half + 1] + bias.y;
                *(float2*)(orow + n) = v;
            }
        }
    }
}

extern "C" void kernel_launch(void* const* d_in, const int* in_sizes, int n_in,
                              void* d_out, int out_size)
{
    const float* features = (const float*)d_in[0];
    const int*   captions = (const int*)d_in[1];
    const float* embed_W  = (const float*)d_in[2];
    const float* ihW = (const float*)d_in[3];
    const float* ihb = (const float*)d_in[4];
    const float* icW = (const float*)d_in[5];
    const float* icb = (const float*)d_in[6];
    const float* rW  = (const float*)d_in[7];
    const float* rb  = (const float*)d_in[8];
    const float* Wih = (const float*)d_in[9];
    const float* Whh = (const float*)d_in[10];
    const float* bih = (const float*)d_in[11];
    const float* bhh = (const float*)d_in[12];
    const float* outW = (const float*)d_in[13];
    const float* outb = (const float*)d_in[14];

    cudaFuncSetAttribute(recurrence_kernel,
                         cudaFuncAttributeMaxDynamicSharedMemorySize, POOL_BYTES);

    dim3 pgrid(8, 16);
    pre_wf<<<pgrid, 256>>>(Wih, rW);
    pre_bias<<<64, 256>>>(Wih, rb, bih, bhh);
    pre_emb<<<(SEQ * EE * BB) / 256, 256>>>(captions, embed_W);
    recurrence_kernel<<<NBLK, NTHR, POOL_BYTES>>>(features,
                                                  ihW, ihb, icW, icb, Whh);
    convert_kernel<<<2048, 256>>>(outW);
    dim3 grid(VV / 128, (SEQ * BB) / 128);
    out_gemm_tc<<<grid, 256>>>(outb, (float*)d_out);
}

// round 17
// speedup vs baseline: 1.6150x; 1.0530x over previous
#include <cuda_runtime.h>
#include <cuda_bf16.h>
#include <math.h>
#include <stdint.h>

#define BB 32
#define NREG 196
#define EE 512
#define HH 512
#define SEQ 64
#define VV 32000

#define NBLK 148
#define NTHR 512

// dynamic smem pool (floats)
#define OFF_W     0                      // 16*1536 = 24576
#define OFF_ACTA  24576                  // 4096
#define OFF_ACTB  28672                  // 4096
#define OFF_H     32768                  // 512
#define OFF_SC    33280                  // 256
#define OFF_ATTN  33536                  // 256
#define OFF_REDS  33792                  // 64
#define OFF_PART  33856                  // 2048 (16*128)
#define OFF_RED   35904                  // 4096 (16 rows * 8 qq * 32 b)
#define OFF_OUT   40000                  // 512
#define POOL_F    40512
#define POOL_BYTES (POOL_F * 4)

// ---------------- scratch (device globals; no allocations) ----------------
__device__ float g_fmean[BB * EE];
__device__ __align__(16) float g_hbuf[2][BB * HH];   // [b][k]
__device__ __align__(16) float g_hT[2][HH * BB];     // [k][b]
__device__ float g_cT[HH * BB];                      // [k][b]
__device__ __align__(16) float g_ctxT[EE * BB];      // [k][b] context
__device__ __align__(16) float g_embT[SEQ * EE * BB];// [t][k][b] emb*sqrtE, 4MB
__device__ __align__(16) float g_Hall[SEQ * BB * HH];
__device__ __align__(16) float g_Wf[4 * HH * (EE + HH)]; // fused Wih@rW, rp-ordered rows
__device__ float g_bf[4 * HH];
__device__ unsigned g_bar_count;
__device__ unsigned g_bar_gen;

// bf16 split buffers for tensor-core GEMM
__device__ __align__(16) __nv_bfloat16 g_AH[SEQ * BB * HH];
__device__ __align__(16) __nv_bfloat16 g_AL[SEQ * BB * HH];
__device__ __align__(16) __nv_bfloat16 g_WH[(size_t)VV * EE];
__device__ __align__(16) __nv_bfloat16 g_WL[(size_t)VV * EE];

// ---------------- grid-wide barrier ----------------
__device__ __forceinline__ void gridbar() {
    __syncthreads();
    if (threadIdx.x == 0) {
        unsigned gen = *((volatile unsigned*)&g_bar_gen);
        __threadfence();
        if (atomicAdd(&g_bar_count, 1u) == (unsigned)(gridDim.x - 1)) {
            g_bar_count = 0;
            __threadfence();
            atomicAdd(&g_bar_gen, 1u);
        } else {
            while (*((volatile unsigned*)&g_bar_gen) == gen) { __nanosleep(32); }
        }
        __threadfence();
    }
    __syncthreads();
}

__device__ __forceinline__ float warpsum(float v) {
#pragma unroll
    for (int o = 16; o; o >>= 1) v += __shfl_xor_sync(0xffffffffu, v, o);
    return v;
}

__device__ __forceinline__ void warpsum2(float& a, float& b) {
#pragma unroll
    for (int o = 16; o; o >>= 1) {
        a += __shfl_xor_sync(0xffffffffu, a, o);
        b += __shfl_xor_sync(0xffffffffu, b, o);
    }
}

__device__ __forceinline__ float warpdot512(const float* __restrict__ a,
                                            const float* __restrict__ b, int lane) {
    float s = 0.f;
#pragma unroll
    for (int c = 0; c < 4; c++) {
        float4 av = *(const float4*)(a + c * 128 + lane * 4);
        float4 bv = *(const float4*)(b + c * 128 + lane * 4);
        s += av.x * bv.x + av.y * bv.y + av.z * bv.z + av.w * bv.w;
    }
    return s;
}

// ---------------- precompute: embeddings for all steps ----------------
__global__ void __launch_bounds__(256) pre_emb(const int* __restrict__ captions,
                                               const float* __restrict__ embed_W)
{
    int idx = blockIdx.x * 256 + threadIdx.x;
    int b = idx & 31;
    int k = (idx >> 5) & 511;
    int t = idx >> 14;
    int tok = captions[b * SEQ + t];
    g_embT[idx] = embed_W[(size_t)tok * EE + k] * 22.62741699796952f;
}

// ---------------- precompute: Wf = Wih @ rW (rows permuted to rp order) ----------------
__global__ void __launch_bounds__(256) pre_wf(const float* __restrict__ Wih,
                                              const float* __restrict__ rW)
{
    __shared__ __align__(16) float As[16][128];
    __shared__ __align__(16) float Bs[16][128];
    const int bn = blockIdx.x;
    const int bm = blockIdx.y;
    const int tid = threadIdx.x;
    const int tx = tid & 15, ty = tid >> 4;

    float acc[8][8];
#pragma unroll
    for (int i = 0; i < 8; i++)
#pragma unroll
        for (int j = 0; j < 8; j++) acc[i][j] = 0.f;

    for (int k0 = 0; k0 < 512; k0 += 16) {
#pragma unroll
        for (int i = 0; i < 2; i++) {
            int f = tid + i * 256;
            int row = f >> 2;
            int cg  = (f & 3) * 4;
            int m = bm * 128 + row;
            int arow = (m & 3) * HH + (m >> 2);
            float4 va = *(const float4*)(Wih + (size_t)arow * EE + k0 + cg);
            As[cg + 0][row] = va.x; As[cg + 1][row] = va.y;
            As[cg + 2][row] = va.z; As[cg + 3][row] = va.w;
            int kk = f >> 5;
            int n4 = (f & 31) * 4;
            float4 vb = *(const float4*)(rW + (size_t)(k0 + kk) * (EE + HH) + bn * 128 + n4);
            *(float4*)&Bs[kk][n4] = vb;
        }
        __syncthreads();
#pragma unroll
        for (int kk = 0; kk < 16; kk++) {
            float a[8], b[8];
#pragma unroll
            for (int i = 0; i < 8; i += 4) {
                float4 v = *(const float4*)&As[kk][ty * 8 + i];
                a[i] = v.x; a[i + 1] = v.y; a[i + 2] = v.z; a[i + 3] = v.w;
            }
#pragma unroll
            for (int j = 0; j < 8; j += 4) {
                float4 v = *(const float4*)&Bs[kk][tx * 8 + j];
                b[j] = v.x; b[j + 1] = v.y; b[j + 2] = v.z; b[j + 3] = v.w;
            }
#pragma unroll
            for (int i = 0; i < 8; i++)
#pragma unroll
                for (int j = 0; j < 8; j++) acc[i][j] += a[i] * b[j];
        }
        __syncthreads();
    }
#pragma unroll
    for (int i = 0; i < 8; i++) {
        int m = bm * 128 + ty * 8 + i;
        float* crow = g_Wf + (size_t)m * (EE + HH) + bn * 128 + tx * 8;
#pragma unroll
        for (int j = 0; j < 8; j += 4) {
            float4 v;
            v.x = acc[i][j]; v.y = acc[i][j + 1]; v.z = acc[i][j + 2]; v.w = acc[i][j + 3];
            *(float4*)(crow + j) = v;
        }
    }
}

__global__ void __launch_bounds__(256) pre_bias(const float* __restrict__ Wih,
                                                const float* __restrict__ rb,
                                                const float* __restrict__ bih,
                                                const float* __restrict__ bhh)
{
    int lane = threadIdx.x & 31;
    int wid_g = (blockIdx.x * 256 + threadIdx.x) >> 5;
    int nw = (gridDim.x * 256) >> 5;
    for (int r = wid_g; r < 4 * HH; r += nw) {
        float s = warpsum(warpdot512(Wih + (size_t)r * EE, rb, lane));
        if (lane == 0) g_bf[r] = s + bih[r] + bhh[r];
    }
}

// ---------------- persistent recurrence kernel ----------------
__global__ void __launch_bounds__(NTHR) recurrence_kernel(
    const float* __restrict__ features,
    const float* __restrict__ ihW, const float* __restrict__ ihb,
    const float* __restrict__ icW, const float* __restrict__ icb,
    const float* __restrict__ Whh)
{
    extern __shared__ __align__(16) float pool[];
    float* wSmem = pool + OFF_W;
    float* actA  = pool + OFF_ACTA;
    float* actB  = pool + OFF_ACTB;
    float* sh_h  = pool + OFF_H;
    float* sSc   = pool + OFF_SC;
    float* sAttn = pool + OFF_ATTN;
    float* sRedS = pool + OFF_REDS;
    float* sPart = pool + OFF_PART;
    float* sRed  = pool + OFF_RED;
    float* sOut  = pool + OFF_OUT;

    const int tid  = threadIdx.x;
    const int lane = tid & 31;
    const int w    = tid >> 5;
    const int gtid = blockIdx.x * NTHR + tid;
    const int wid_g  = gtid >> 5;
    const int nwarps = (NBLK * NTHR) >> 5;
    const int gstride = NBLK * NTHR;

    // ---- init a: fmean
    for (int idx = gtid; idx < BB * EE; idx += gstride) {
        int b = idx >> 9, e = idx & 511;
        const float* fp = features + (size_t)b * NREG * EE + e;
        float s = 0.f;
        for (int n = 0; n < NREG; n++) s += fp[n * EE];
        g_fmean[idx] = s * (1.0f / NREG);
    }
    gridbar();

    // ---- init b: h0 / c0
    for (int task = wid_g; task < 2 * BB * HH; task += nwarps) {
        int which = task & 1;
        int m = task >> 1;
        int b = m >> 9, eo = m & 511;
        const float* Wrow = (which ? icW : ihW) + (size_t)eo * EE;
        float s = warpsum(warpdot512(Wrow, g_fmean + b * EE, lane));
        if (lane == 0) {
            if (which) {
                g_cT[eo * BB + b] = s + icb[eo];
            } else {
                float hv = s + ihb[eo];
                g_hbuf[0][m] = hv;
                g_hT[0][eo * BB + b] = hv;
            }
        }
    }

    // ---- load this block's 16 gate rows (1536 wide) into persistent smem
    if (blockIdx.x < 128) {
        const int rp0 = blockIdx.x * 16;
        for (int i4 = tid; i4 < 6144; i4 += NTHR) {
            int elem = i4 * 4;
            int rl  = elem / 1536;
            int off = elem - rl * 1536;
            float4 v;
            if (off < 1024) {
                v = *(const float4*)(g_Wf + (size_t)(rp0 + rl) * (EE + HH) + off);
            } else {
                int rp = rp0 + rl;
                int hi = rp >> 2, gate = rp & 3;
                v = *(const float4*)(Whh + (size_t)(gate * HH + hi) * HH + (off - 1024));
            }
            *(float4*)(wSmem + rl * 1536 + off) = v;
        }
    }
    gridbar();

    for (int t = 0; t < SEQ; t++) {
        const float* h_cur  = g_hbuf[t & 1];
        const float* hT_cur = g_hT[t & 1];
        float*       h_nxt  = g_hbuf[(t & 1) ^ 1];
        float*       hT_nxt = g_hT[(t & 1) ^ 1];

        // ==== P12: attention (scores redundant per (b,chunk) block)
        if (blockIdx.x < 128) {
            const int b = blockIdx.x >> 2;
            const int chunk = blockIdx.x & 3;
            const float* fb = features + (size_t)b * NREG * EE;

            sh_h[tid] = h_cur[b * EE + tid];
            __syncthreads();

            for (int n0i = w; n0i < NREG; n0i += 32) {
                int n1i = n0i + 16;
                bool has1 = (n1i < NREG);
                const float* f0 = fb + (size_t)n0i * EE;
                const float* f1 = fb + (size_t)(has1 ? n1i : n0i) * EE;
                float s0 = 0.f, s1 = 0.f;
#pragma unroll
                for (int c = 0; c < 4; c++) {
                    float4 hv = *(const float4*)(sh_h + c * 128 + lane * 4);
                    float4 a0 = *(const float4*)(f0 + c * 128 + lane * 4);
                    float4 a1 = *(const float4*)(f1 + c * 128 + lane * 4);
                    s0 += a0.x * hv.x + a0.y * hv.y + a0.z * hv.z + a0.w * hv.w;
                    s1 += a1.x * hv.x + a1.y * hv.y + a1.z * hv.z + a1.w * hv.w;
                }
                warpsum2(s0, s1);
                if (lane == 0) {
                    sSc[n0i] = s0;
                    if (has1) sSc[n1i] = s1;
                }
            }
            __syncthreads();

            float v = (tid < NREG) ? sSc[tid] : -1e30f;
            float m = v;
#pragma unroll
            for (int o = 16; o; o >>= 1) m = fmaxf(m, __shfl_xor_sync(0xffffffffu, m, o));
            if (lane == 0) sRedS[w] = m;
            __syncthreads();
            float mx = sRedS[0];
#pragma unroll
            for (int i = 1; i < 16; i++) mx = fmaxf(mx, sRedS[i]);
            float ev = (tid < NREG) ? __expf(v - mx) : 0.f;
            float ps = warpsum(ev);
            __syncthreads();
            if (lane == 0) sRedS[w] = ps;
            __syncthreads();
            float tot = 0.f;
#pragma unroll
            for (int i = 0; i < 16; i++) tot += sRedS[i];
            if (tid < NREG) sAttn[tid] = ev / tot;
            __syncthreads();

            float4 cacc = make_float4(0.f, 0.f, 0.f, 0.f);
            const float* fc = fb + chunk * 128 + lane * 4;
#pragma unroll 4
            for (int n = w; n < NREG; n += 16) {
                float a = sAttn[n];
                float4 fv = *(const float4*)(fc + (size_t)n * EE);
                cacc.x += a * fv.x; cacc.y += a * fv.y;
                cacc.z += a * fv.z; cacc.w += a * fv.w;
            }
            *(float4*)(sPart + w * 128 + lane * 4) = cacc;
            __syncthreads();
            if (tid < 128) {
                float s = 0.f;
#pragma unroll
                for (int i = 0; i < 16; i++) s += sPart[i * 128 + tid];
                g_ctxT[(chunk * 128 + tid) * BB + b] = s;
            }
        }
        gridbar();

        // ==== P4': fused gates + cell. warp = (8-row group, k-sixteenth of chunk)
        if (blockIdx.x < 128) {
            const int rg = w >> 3;          // 0..1 : 8-row group
            const int qq = w & 7;           // 0..7 : 16-k slice within 128-k chunk
            float acc[8];
#pragma unroll
            for (int r = 0; r < 8; r++) acc[r] = 0.f;
            const float* embT_t = g_embT + (size_t)t * EE * BB;

            for (int i4 = tid; i4 < 1024; i4 += NTHR)
                ((float4*)actA)[i4] = ((const float4*)g_ctxT)[i4];
            __syncthreads();

            for (int kc = 0; kc < 12; kc++) {
                float* cur = (kc & 1) ? actB : actA;
                float* nxt = (kc & 1) ? actA : actB;
                if (kc < 11) {
                    int kn = kc + 1;
                    const float* asrc = (kn < 4) ? (g_ctxT + kn * 128 * BB)
                                      : (kn < 8) ? (embT_t + (kn - 4) * 128 * BB)
                                                 : (hT_cur + (kn - 8) * 128 * BB);
                    for (int i4 = tid; i4 < 1024; i4 += NTHR)
                        ((float4*)nxt)[i4] = ((const float4*)asrc)[i4];
                }
                const float* wbase = wSmem + (rg * 8) * 1536 + kc * 128 + qq * 16;
#pragma unroll
                for (int k4 = 0; k4 < 16; k4 += 4) {
                    const float* ap = cur + (qq * 16 + k4) * BB + lane;
                    float a0 = ap[0 * BB], a1 = ap[1 * BB];
                    float a2 = ap[2 * BB], a3 = ap[3 * BB];
#pragma unroll
                    for (int r = 0; r < 8; r++) {
                        float4 wv = *(const float4*)(wbase + r * 1536 + k4);
                        acc[r] += wv.x * a0 + wv.y * a1 + wv.z * a2 + wv.w * a3;
                    }
                }
                __syncthreads();
            }
#pragma unroll
            for (int r = 0; r < 8; r++)
                sRed[((rg * 8 + r) * 8 + qq) * BB + lane] = acc[r];
            __syncthreads();
            {
                int rl = tid >> 5, b = tid & 31;     // all 512 threads: 16 rows x 32 b
                float s = 0.f;
#pragma unroll
                for (int i = 0; i < 8; i++) s += sRed[(rl * 8 + i) * BB + b];
                sOut[rl * BB + b] = s;
            }
            __syncthreads();
            if (tid < 128) {
                int hl = tid >> 5;
                int b  = tid & 31;
                int hi = blockIdx.x * 4 + hl;
                float iv = sOut[(hl * 4 + 0) * BB + b] + g_bf[hi];
                float fv = sOut[(hl * 4 + 1) * BB + b] + g_bf[HH + hi];
                float gv = sOut[(hl * 4 + 2) * BB + b] + g_bf[2 * HH + hi];
                float ov = sOut[(hl * 4 + 3) * BB + b] + g_bf[3 * HH + hi];
                float si = 1.f / (1.f + __expf(-iv));
                float sf = 1.f / (1.f + __expf(-fv));
                float so = 1.f / (1.f + __expf(-ov));
                float c2 = sf * g_cT[hi * BB + b] + si * tanhf(gv);
                float h2 = so * tanhf(c2);
                g_cT[hi * BB + b] = c2;
                hT_nxt[hi * BB + b] = h2;
                h_nxt[b * HH + hi] = h2;
                g_Hall[((size_t)t * BB + b) * HH + hi] = h2;
            }
        }
        gridbar();
    }
}

// ---------------- fp32 -> bf16 hi/lo split ----------------
__device__ __forceinline__ void split_store(float4 v, __nv_bfloat16* H,
                                            __nv_bfloat16* L, size_t off) {
    __nv_bfloat162 h0, h1, l0, l1;
    h0.x = __float2bfloat16(v.x); h0.y = __float2bfloat16(v.y);
    h1.x = __float2bfloat16(v.z); h1.y = __float2bfloat16(v.w);
    l0.x = __float2bfloat16(v.x - __bfloat162float(h0.x));
    l0.y = __float2bfloat16(v.y - __bfloat162float(h0.y));
    l1.x = __float2bfloat16(v.z - __bfloat162float(h1.x));
    l1.y = __float2bfloat16(v.w - __bfloat162float(h1.y));
    *(__nv_bfloat162*)(H + off) = h0; *(__nv_bfloat162*)(H + off + 2) = h1;
    *(__nv_bfloat162*)(L + off) = l0; *(__nv_bfloat162*)(L + off + 2) = l1;
}

__global__ void __launch_bounds__(256) convert_kernel(const float* __restrict__ outW)
{
    const size_t NW4 = ((size_t)VV * EE) / 4;
    const size_t NA4 = ((size_t)SEQ * BB * HH) / 4;
    size_t stride = (size_t)gridDim.x * blockDim.x;
    for (size_t i = (size_t)blockIdx.x * blockDim.x + threadIdx.x;
         i < NW4 + NA4; i += stride) {
        if (i < NW4) {
            float4 v = ((const float4*)outW)[i];
            split_store(v, g_WH, g_WL, i * 4);
        } else {
            size_t j = i - NW4;
            float4 v = ((const float4*)g_Hall)[j];
            split_store(v, g_AH, g_AL, j * 4);
        }
    }
}

// ---------------- tensor-core output GEMM ----------------
#define LDSW 40

__device__ __forceinline__ uint32_t s2u(const void* p) {
    return (uint32_t)__cvta_generic_to_shared(p);
}
__device__ __forceinline__ void ldsm_x4(uint32_t r[4], uint32_t addr) {
    asm volatile("ldmatrix.sync.aligned.m8n8.x4.shared.b16 {%0,%1,%2,%3}, [%4];"
                 : "=r"(r[0]), "=r"(r[1]), "=r"(r[2]), "=r"(r[3]) : "r"(addr));
}
__device__ __forceinline__ void mma_bf16(float c[4], const uint32_t a[4], const uint32_t b[2]) {
    asm volatile("mma.sync.aligned.m16n8k16.row.col.f32.bf16.bf16.f32 "
                 "{%0,%1,%2,%3}, {%4,%5,%6,%7}, {%8,%9}, {%0,%1,%2,%3};"
                 : "+f"(c[0]), "+f"(c[1]), "+f"(c[2]), "+f"(c[3])
                 : "r"(a[0]), "r"(a[1]), "r"(a[2]), "r"(a[3]), "r"(b[0]), "r"(b[1]));
}

__global__ void __launch_bounds__(256) out_gemm_tc(
    const float* __restrict__ outb, float* __restrict__ out)
{
    __shared__ __align__(16) __nv_bfloat16 sAH[128 * LDSW];
    __shared__ __align__(16) __nv_bfloat16 sAL[128 * LDSW];
    __shared__ __align__(16) __nv_bfloat16 sBH[128 * LDSW];
    __shared__ __align__(16) __nv_bfloat16 sBL[128 * LDSW];

    const int tid  = threadIdx.x;
    const int lane = tid & 31;
    const int w    = tid >> 5;
    const int wm   = w >> 2;
    const int wn   = w & 3;
    const int m0 = blockIdx.y * 128;
    const int n0 = blockIdx.x * 128;

    float acc[4][4][4];
#pragma unroll
    for (int mt = 0; mt < 4; mt++)
#pragma unroll
        for (int nt = 0; nt < 4; nt++)
#pragma unroll
            for (int r = 0; r < 4; r++) acc[mt][nt][r] = 0.f;

    const int a_row = lane & 15;
    const int a_k8  = (lane >> 4) * 8;
    const int b_nrw = (lane & 7) + ((lane >> 4) << 3);
    const int b_k8  = ((lane >> 3) & 1) * 8;

    const uint32_t uAH = s2u(sAH), uAL = s2u(sAL);
    const uint32_t uBH = s2u(sBH), uBL = s2u(sBL);

    for (int k0 = 0; k0 < 512; k0 += 32) {
        __syncthreads();
#pragma unroll
        for (int i = 0; i < 2; i++) {
            int v = tid + i * 256;
            int row = v >> 2;
            int kc  = (v & 3) * 8;
            size_t ga = (size_t)(m0 + row) * 512 + k0 + kc;
            size_t gb = (size_t)(n0 + row) * 512 + k0 + kc;
            int so = row * LDSW + kc;
            *(uint4*)(sAH + so) = *(const uint4*)(g_AH + ga);
            *(uint4*)(sAL + so) = *(const uint4*)(g_AL + ga);
            *(uint4*)(sBH + so) = *(const uint4*)(g_WH + gb);
            *(uint4*)(sBL + so) = *(const uint4*)(g_WL + gb);
        }
        __syncthreads();

#pragma unroll
        for (int ks = 0; ks < 32; ks += 16) {
            uint32_t aH[4][4], aL[4][4];
#pragma unroll
            for (int mt = 0; mt < 4; mt++) {
                int off = ((wm * 64 + mt * 16 + a_row) * LDSW + ks + a_k8) * 2;
                ldsm_x4(aH[mt], uAH + off);
                ldsm_x4(aL[mt], uAL + off);
            }
            uint32_t bH[4][2], bL[4][2];
#pragma unroll
            for (int p = 0; p < 2; p++) {
                int off = ((wn * 32 + p * 16 + b_nrw) * LDSW + ks + b_k8) * 2;
                uint32_t r[4];
                ldsm_x4(r, uBH + off);
                bH[2 * p][0] = r[0]; bH[2 * p][1] = r[1];
                bH[2 * p + 1][0] = r[2]; bH[2 * p + 1][1] = r[3];
                ldsm_x4(r, uBL + off);
                bL[2 * p][0] = r[0]; bL[2 * p][1] = r[1];
                bL[2 * p + 1][0] = r[2]; bL[2 * p + 1][1] = r[3];
            }
#pragma unroll
            for (int mt = 0; mt < 4; mt++)
#pragma unroll
                for (int nt = 0; nt < 4; nt++) {
                    mma_bf16(acc[mt][nt], aH[mt], bH[nt]);
                    mma_bf16(acc[mt][nt], aH[mt], bL[nt]);
                    mma_bf16(acc[mt][nt], aL[mt], bH[nt]);
                }
        }
    }

#pragma unroll
    for (int mt = 0; mt < 4; mt++) {
#pragma unroll
        for (int half = 0; half < 2; half++) {
            int m = m0 + wm * 64 + mt * 16 + (lane >> 2) + half * 8;
            int tt = m >> 5, b = m & 31;
            float* orow = out + ((size_t)b * SEQ + tt) * VV;
#pragma unroll
            for (int nt = 0; nt < 4; nt++) {
                int n = n0 + wn * 32 + nt * 8 + 2 * (lane & 3);
                float2 bias = *(const float2*)(outb + n);
                float2 v;
                v.x = acc[mt][nt][2 * half + 0] + bias.x;
                v.y = acc[mt][nt][2 * half + 1] + bias.y;
                *(float2*)(orow + n) = v;
            }
        }
    }
}

extern "C" void kernel_launch(void* const* d_in, const int* in_sizes, int n_in,
                              void* d_out, int out_size)
{
    const float* features = (const float*)d_in[0];
    const int*   captions = (const int*)d_in[1];
    const float* embed_W  = (const float*)d_in[2];
    const float* ihW = (const float*)d_in[3];
    const float* ihb = (const float*)d_in[4];
    const float* icW = (const float*)d_in[5];
    const float* icb = (const float*)d_in[6];
    const float* rW  = (const float*)d_in[7];
    const float* rb  = (const float*)d_in[8];
    const float* Wih = (const float*)d_in[9];
    const float* Whh = (const float*)d_in[10];
    const float* bih = (const float*)d_in[11];
    const float* bhh = (const float*)d_in[12];
    const float* outW = (const float*)d_in[13];
    const float* outb = (const float*)d_in[14];

    cudaFuncSetAttribute(recurrence_kernel,
                         cudaFuncAttributeMaxDynamicSharedMemorySize, POOL_BYTES);

    dim3 pgrid(8, 16);
    pre_wf<<<pgrid, 256>>>(Wih, rW);
    pre_bias<<<64, 256>>>(Wih, rb, bih, bhh);
    pre_emb<<<(SEQ * EE * BB) / 256, 256>>>(captions, embed_W);
    recurrence_kernel<<<NBLK, NTHR, POOL_BYTES>>>(features,
                                                  ihW, ihb, icW, icb, Whh);
    convert_kernel<<<2048, 256>>>(outW);
    dim3 grid(VV / 128, (SEQ * BB) / 128);
    out_gemm_tc<<<grid, 256>>>(outb, (float*)d_out);
}